// round 13
// baseline (speedup 1.0000x reference)
#include <cuda_runtime.h>
#include <cuda.h>
#include <cstdint>

// ============================================================================
// PHM8Linear: out[131072,512] = X[131072,512] @ H[512,512]^T + bias
// H[a*64+b][c*64+d] = sum_i A[i,a,c] * S[i,b,d]
// tcgen05 TF32 cta_group::2 SS GEMM, persistent grid=148, cluster (2,1,1).
// R13: build_H emits g_Hsw = pre-swizzled SW128 smem images, fetched via
// SWIZZLE_NONE TMA with 1024B rows (32 rows/stage instead of 256) to cut
// per-SM TMA row-processing load. X keeps the swizzled TMA path.
// Rings: X 6x16KB, H 4x32KB. Epilogue split per N-half, lookahead-4 D0 burst.
// X raw fp32 (HW tf32 truncate); H pre-rounded RN in build_H.
// ============================================================================

#define N_F    512
#define KC     32          // K elems per chunk = 128 bytes = SW128 row
#define NXS    6           // X ring depth
#define NHS    4           // H ring depth
#define GRID   148
#define NPAIR  74
#define M_TILES 512        // 131072/256

__device__ float g_H[N_F * N_F];     // row-major H (SIMT fallback only)
__device__ float g_Hsw[N_F * N_F];   // pre-swizzled SW128 images: [kc][rank][b][16KB]

#if defined(__CUDA_ARCH__) && (defined(__CUDA_ARCH_FEAT_SM103_ALL) || \
    defined(__CUDA_ARCH_FEAT_SM100_ALL) || defined(__CUDA_ARCH_FEAT_SM101_ALL))
#define HAS_TCGEN05 1
#else
#define HAS_TCGEN05 0
#endif

// ---------------- smem layout (dynamic), tcgen05 path ----------------
#define OFF_TPTR    0
#define OFF_XFULL(s) (8 + 8 * (s))
#define OFF_XDONE(s) (64 + 8 * (s))
#define OFF_HFULL(s) (120 + 8 * (s))
#define OFF_HDONE(s) (152 + 8 * (s))
#define OFF_EPI0    184
#define OFF_EPI1    192
#define OFF_DFREE0  200
#define OFF_DFREE1  208
#define OFF_XS(s)   (1024 + (s) * 16384)            // 6 x 16KB X stages
#define OFF_HS(s)   (99328 + (s) * 32768)           // 4 x 32KB H stages (H0|H1)
#define SMEM_BYTES  230400
#define EXPECT_X    32768u   // 16KB x 2 CTAs onto leader's barrier
#define EXPECT_H    65536u   // 32KB x 2 CTAs

// idesc: kind::tf32, D=F32(1<<4), A=TF32(2<<7), B=TF32(2<<10), N=256, M=256
#define IDESC_TF32_CG2 ((1u << 4) | (2u << 7) | (2u << 10) | ((256u / 8u) << 17) | ((256u / 16u) << 24))

// K-major SW128 smem descriptor base: layout=SW128(2), version=1, SBO=64, LBO=1
static __device__ __host__ constexpr uint64_t DESC_BASE_SW128 =
    (uint64_t(2) << 61) | (uint64_t(1) << 46) | (uint64_t(64) << 32) | (uint64_t(1) << 16);

__device__ __forceinline__ uint32_t s2u(const void* p) {
    uint32_t a;
    asm("{ .reg .u64 t; cvta.to.shared.u64 t, %1; cvt.u32.u64 %0, t; }" : "=r"(a) : "l"(p));
    return a;
}

#define MBAR_INIT(addr, cnt) \
    asm volatile("mbarrier.init.shared.b64 [%0], %1;" :: "r"(addr), "r"(cnt) : "memory")

#define MBAR_ARRIVE(addr) \
    asm volatile("mbarrier.arrive.shared.b64 _, [%0];" :: "r"(addr) : "memory")

// Arrive on the same-offset mbarrier in cluster CTA rank 0.
#define MBAR_ARRIVE_CLUSTER0(addr)                                             \
    asm volatile("{\n\t.reg .b32 ra;\n\t"                                      \
        "mapa.shared::cluster.u32 ra, %0, %1;\n\t"                             \
        "mbarrier.arrive.shared::cluster.b64 _, [ra];\n\t}"                    \
        :: "r"(addr), "r"(0) : "memory")

#define MBAR_EXPECT_TX(addr, bytes) \
    asm volatile("mbarrier.arrive.expect_tx.shared.b64 _, [%0], %1;" :: "r"(addr), "r"(bytes) : "memory")

#define MBAR_WAIT_SCOPE(addr, parity, SCOPE) do {                              \
    uint32_t _mb = (addr); uint32_t _ph = (parity); uint32_t _dn;              \
    asm volatile("{\n\t.reg .pred p;\n\t"                                      \
        "mbarrier.try_wait.parity.acquire." SCOPE ".shared::cta.b64 p, [%1], %2;\n\t" \
        "selp.b32 %0, 1, 0, p;\n\t}" : "=r"(_dn) : "r"(_mb), "r"(_ph) : "memory"); \
    while (!_dn) {                                                             \
        asm volatile("{\n\t.reg .pred p;\n\t"                                  \
            "mbarrier.try_wait.parity.acquire." SCOPE ".shared::cta.b64 p, [%1], %2, 0x989680;\n\t" \
            "selp.b32 %0, 1, 0, p;\n\t}" : "=r"(_dn) : "r"(_mb), "r"(_ph) : "memory"); \
    }                                                                          \
} while (0)

#define MBAR_WAIT(addr, parity)     MBAR_WAIT_SCOPE(addr, parity, "cta")
#define MBAR_WAIT_CLU(addr, parity) MBAR_WAIT_SCOPE(addr, parity, "cluster")

// cta_group::2 TMA (3D): completes on leader's barrier (bit 24 cleared).
#define TMA3D_CG2(smem, map, cx, cy, cz, mbar)                                 \
    asm volatile("{\n\t.reg .b32 lb;\n\t"                                      \
        "and.b32 lb, %5, 0xFEFFFFFF;\n\t"                                      \
        "cp.async.bulk.tensor.3d.cta_group::2.shared::cluster.global"          \
        ".tile.mbarrier::complete_tx::bytes [%0], [%1, {%2, %3, %4}], [lb];\n\t}" \
        :: "r"(smem), "l"(map), "r"(cx), "r"(cy), "r"(cz), "r"(mbar) : "memory")

// cta_group::2 TMA (2D) — used for the pre-swizzled H fetch.
#define TMA2D_CG2(smem, map, cx, cy, mbar)                                     \
    asm volatile("{\n\t.reg .b32 lb;\n\t"                                      \
        "and.b32 lb, %4, 0xFEFFFFFF;\n\t"                                      \
        "cp.async.bulk.tensor.2d.cta_group::2.shared::cluster.global"          \
        ".tile.mbarrier::complete_tx::bytes [%0], [%1, {%2, %3}], [lb];\n\t}"  \
        :: "r"(smem), "l"(map), "r"(cx), "r"(cy), "r"(mbar) : "memory")

// cta_group::2 tf32 MMA (leader issues; A/B split across the CTA pair)
#define MMA_TF32_CG2(dst, adsc, bdsc, en)                                      \
    asm volatile("{\n\t.reg .pred p;\n\tsetp.ne.u32 p, %5, 0;\n\t"             \
        "tcgen05.mma.cta_group::2.kind::tf32 [%0], %1, %2, %3, "               \
        "{%4,%4,%4,%4,%4,%4,%4,%4}, p;\n\t}"                                   \
        :: "r"(dst), "l"(adsc), "l"(bdsc), "r"(IDESC_TF32_CG2), "r"(0u), "r"(en) : "memory")

#define TC_COMMIT_MC_CG2(mbar)                                                 \
    asm volatile("tcgen05.commit.cta_group::2.mbarrier::arrive::one.shared::cluster.multicast::cluster.b64 [%0], %1;" \
        :: "r"(mbar), "h"((uint16_t)3) : "memory")

#define CLUSTER_SYNC() do {                                                    \
    asm volatile("barrier.cluster.arrive.aligned;" ::: "memory");              \
    asm volatile("barrier.cluster.wait.aligned;" ::: "memory");                \
} while (0)

// ---------------------------------------------------------------------------
// H precompute: H[r=a*64+b][k=c*64+d] = sum_i A[i,a,c]*S[i,b,d], RN->tf32.
// Writes row-major g_H (fallback) AND g_Hsw: the SW128 smem byte image,
// segmented [kc=k/32][rank=rowInBlock/128] (32KB each: block0 16KB | block1
// 16KB), so one linear 2D TMA (1024B rows) reproduces the swizzled image.
// ---------------------------------------------------------------------------
__global__ void build_H(const float* __restrict__ A, const float* __restrict__ S) {
    int r = blockIdx.x;     // 0..511
    int k = threadIdx.x;    // 0..511
    int a = r >> 6, bb = r & 63, c = k >> 6, d = k & 63;
    float acc = 0.f;
#pragma unroll
    for (int i = 0; i < 8; i++)
        acc = fmaf(A[i * 64 + a * 8 + c], S[i * 4096 + bb * 64 + d], acc);
    uint32_t t;
    asm("cvt.rna.tf32.f32 %0, %1;" : "=r"(t) : "f"(acc));
    float v = __uint_as_float(t);
    g_H[r * N_F + k] = v;

    int kc  = k >> 5;            // k-chunk 0..15
    int col = k & 31;            // col within chunk
    int b   = r >> 8;            // column block 0/1
    int rib = r & 255;           // row in block
    int rr  = rib >> 7;          // rank half
    int row = rib & 127;         // row within 128-row half
    uint32_t off = (uint32_t)(kc * 2 + rr) * 32768u + (uint32_t)b * 16384u;
    uint32_t bo  = (uint32_t)(row * 128 + col * 4);
    bo = bo ^ ((bo >> 3) & 0x70);            // SW128 swizzle
    *reinterpret_cast<float*>(reinterpret_cast<char*>(g_Hsw) + off + bo) = v;
}

// ---------------------------------------------------------------------------
// Main GEMM kernel
// ---------------------------------------------------------------------------
__global__ void __launch_bounds__(256, 1) __cluster_dims__(2, 1, 1) phm_gemm(
    const float* __restrict__ x,
    const float* __restrict__ bias, float* __restrict__ out,
    int ntiles,
    const __grid_constant__ CUtensorMap mx,
    const __grid_constant__ CUtensorMap mh)
{
    int bid = blockIdx.x;

#if HAS_TCGEN05
    // =================== tcgen05 TF32 cg2 path (sm_103a) ==================
    (void)x; (void)ntiles;
    extern __shared__ char smem_raw[];
    uint32_t sb = s2u(smem_raw);
    int tid = threadIdx.x, wid = tid >> 5, lid = tid & 31;

    int c    = bid >> 1;        // pair id (0..73)
    int rank = bid & 1;         // cluster rank
    int cnt  = 1 + (M_TILES - 1 - c) / NPAIR;   // tiles for this pair

    if (wid == 0) {
        asm volatile("tcgen05.alloc.cta_group::2.sync.aligned.shared::cta.b32 [%0], %1;"
                     :: "r"(sb + OFF_TPTR), "r"(512) : "memory");
        asm volatile("tcgen05.relinquish_alloc_permit.cta_group::2.sync.aligned;");
    }
    if (tid == 0) {
#pragma unroll
        for (int s = 0; s < NXS; s++) {
            MBAR_INIT(sb + OFF_XFULL(s), 1);
            MBAR_INIT(sb + OFF_XDONE(s), 1);
        }
#pragma unroll
        for (int s = 0; s < NHS; s++) {
            MBAR_INIT(sb + OFF_HFULL(s), 1);
            MBAR_INIT(sb + OFF_HDONE(s), 1);
        }
        MBAR_INIT(sb + OFF_EPI0, 1);
        MBAR_INIT(sb + OFF_EPI1, 1);
        MBAR_INIT(sb + OFF_DFREE0, 12);      // 6 epilogue warps x 2 CTAs
        MBAR_INIT(sb + OFF_DFREE1, 12);
    }
    __syncthreads();
    uint32_t tmem;
    asm volatile("ld.shared.b32 %0, [%1];" : "=r"(tmem) : "r"(sb + OFF_TPTR));

    // All mbarriers live in both CTAs before any cross-CTA TMA/commit.
    CLUSTER_SYNC();

    if (wid == 0 && lid == 0 && rank == 0) {
        // ---------------- MMA dispatcher (leader only) ----------------
        uint64_t dX[NXS], dH0[NHS], dH1[NHS];
#pragma unroll
        for (int s = 0; s < NXS; s++)
            dX[s]  = DESC_BASE_SW128 | (((sb + OFF_XS(s)) >> 4) & 0x3FFF);
#pragma unroll
        for (int s = 0; s < NHS; s++) {
            dH0[s] = DESC_BASE_SW128 | (((sb + OFF_HS(s))         >> 4) & 0x3FFF);
            dH1[s] = DESC_BASE_SW128 | (((sb + OFF_HS(s) + 16384) >> 4) & 0x3FFF);
        }
        int xs = 0, xph = 0, hs = 0, hph = 0;   // full-wait ring cursors
        for (int j = 0; j < cnt; j++) {
            int sx[4], sh[4];
            // ---- phase A: positions 0..3, D0 MMAs (overlap epilogue D1 read)
            if (j > 0) {
                MBAR_WAIT(sb + OFF_DFREE0, (j - 1) & 1);
                asm volatile("tcgen05.fence::after_thread_sync;" ::: "memory");
            }
#pragma unroll
            for (int q = 0; q < 4; q++) {
                MBAR_WAIT_CLU(sb + OFF_XFULL(xs), xph);
                MBAR_WAIT_CLU(sb + OFF_HFULL(hs), hph);
#pragma unroll
                for (int ks = 0; ks < 4; ks++)
                    MMA_TF32_CG2(tmem, dX[xs] + 2 * ks, dH0[hs] + 2 * ks, (q | ks) ? 1u : 0u);
                sx[q] = xs; sh[q] = hs;
                if (++xs == NXS) { xs = 0; xph ^= 1; }
                if (++hs == NHS) { hs = 0; hph ^= 1; }
            }
            // ---- phase B: D1 for positions 0..3 + done commits
            if (j > 0) {
                MBAR_WAIT(sb + OFF_DFREE1, (j - 1) & 1);
                asm volatile("tcgen05.fence::after_thread_sync;" ::: "memory");
            }
#pragma unroll
            for (int q = 0; q < 4; q++) {
#pragma unroll
                for (int ks = 0; ks < 4; ks++)
                    MMA_TF32_CG2(tmem + 256, dX[sx[q]] + 2 * ks, dH1[sh[q]] + 2 * ks, (q | ks) ? 1u : 0u);
                TC_COMMIT_MC_CG2(sb + OFF_XDONE(sx[q]));
                TC_COMMIT_MC_CG2(sb + OFF_HDONE(sh[q]));
            }
            // ---- steady positions 4..15
            for (int p = 4; p < 16; p++) {
                MBAR_WAIT_CLU(sb + OFF_XFULL(xs), xph);
                MBAR_WAIT_CLU(sb + OFF_HFULL(hs), hph);
#pragma unroll
                for (int ks = 0; ks < 4; ks++)
                    MMA_TF32_CG2(tmem, dX[xs] + 2 * ks, dH0[hs] + 2 * ks, 1u);
                if (p == 15) TC_COMMIT_MC_CG2(sb + OFF_EPI0);   // D0 final
#pragma unroll
                for (int ks = 0; ks < 4; ks++)
                    MMA_TF32_CG2(tmem + 256, dX[xs] + 2 * ks, dH1[hs] + 2 * ks, 1u);
                TC_COMMIT_MC_CG2(sb + OFF_XDONE(xs));
                TC_COMMIT_MC_CG2(sb + OFF_HDONE(hs));
                if (p == 15) TC_COMMIT_MC_CG2(sb + OFF_EPI1);   // D1 final
                if (++xs == NXS) { xs = 0; xph ^= 1; }
                if (++hs == NHS) { hs = 0; hph ^= 1; }
            }
        }
    } else if (wid == 1 && lid == 0) {
        // ---------------- TMA producer (both ranks) ----------------
        int xs = 0, xph = 0, hs = 0, hph = 0;
        int filled = 0;
        for (int j = 0; j < cnt; j++) {
            int m0 = (c + NPAIR * j) * 256;
            for (int k = 0; k < 16; k++) {
                // X fill (swizzled TMA; 128 rows)
                if (filled >= NXS)
                    MBAR_WAIT(sb + OFF_XDONE(xs), xph ^ 1);
                if (rank == 0)
                    MBAR_EXPECT_TX(sb + OFF_XFULL(xs), EXPECT_X);
                TMA3D_CG2(sb + OFF_XS(xs), &mx, k * KC, m0 + rank * 128, 0,
                          sb + OFF_XFULL(xs));
                // H fill: pre-swizzled linear image, 32 x 1024B rows
                if (filled >= NHS)
                    MBAR_WAIT(sb + OFF_HDONE(hs), hph ^ 1);
                if (rank == 0)
                    MBAR_EXPECT_TX(sb + OFF_HFULL(hs), EXPECT_H);
                TMA2D_CG2(sb + OFF_HS(hs), &mh, 0, (k * 2 + rank) * 32,
                          sb + OFF_HFULL(hs));
                filled++;
                if (++xs == NXS) { xs = 0; xph ^= 1; }
                if (++hs == NHS) { hs = 0; hph ^= 1; }
            }
        }
    } else if (wid >= 2) {
        // ---------------- epilogue warps (2..7, both ranks) ----------------
        // Per half (256 cols = 8 chunks): sp0=warp4 (8), sp1=warp5 (8),
        // sp2=warps2/6 (4+4), sp3=warps3/7 (4+4).
        int sp = wid & 3;
        int nch = (sp < 2) ? 8 : 4;
        int ch0 = (sp < 2) ? 0 : ((wid >= 6) ? 4 : 0);
        for (int j = 0; j < cnt; j++) {
            size_t row = (size_t)((c + NPAIR * j) * 256 + rank * 128 + sp * 32 + lid);
            float* orow = out + row * N_F;
#pragma unroll
            for (int half = 0; half < 2; half++) {
                MBAR_WAIT(sb + (half ? OFF_EPI1 : OFF_EPI0), j & 1);
                asm volatile("tcgen05.fence::after_thread_sync;" ::: "memory");
                for (int cc = 0; cc < nch; cc++) {
                    int c0 = half * 256 + (ch0 + cc) * 32;
                    uint32_t r[32];
                    asm volatile(
                        "tcgen05.ld.sync.aligned.32x32b.x32.b32 "
                        "{%0, %1, %2, %3, %4, %5, %6, %7, "
                        " %8, %9, %10, %11, %12, %13, %14, %15, "
                        " %16, %17, %18, %19, %20, %21, %22, %23, "
                        " %24, %25, %26, %27, %28, %29, %30, %31}, [%32];"
                        : "=r"(r[0]),  "=r"(r[1]),  "=r"(r[2]),  "=r"(r[3]),
                          "=r"(r[4]),  "=r"(r[5]),  "=r"(r[6]),  "=r"(r[7]),
                          "=r"(r[8]),  "=r"(r[9]),  "=r"(r[10]), "=r"(r[11]),
                          "=r"(r[12]), "=r"(r[13]), "=r"(r[14]), "=r"(r[15]),
                          "=r"(r[16]), "=r"(r[17]), "=r"(r[18]), "=r"(r[19]),
                          "=r"(r[20]), "=r"(r[21]), "=r"(r[22]), "=r"(r[23]),
                          "=r"(r[24]), "=r"(r[25]), "=r"(r[26]), "=r"(r[27]),
                          "=r"(r[28]), "=r"(r[29]), "=r"(r[30]), "=r"(r[31])
                        : "r"(tmem + c0));
                    asm volatile("tcgen05.wait::ld.sync.aligned;" ::: "memory");
                    if (cc == nch - 1) {
                        // this half's D cols read into regs -> release dispatcher
                        asm volatile("tcgen05.fence::before_thread_sync;" ::: "memory");
                        if (lid == 0) {
                            uint32_t dfrb = sb + (half ? OFF_DFREE1 : OFF_DFREE0);
                            if (rank == 0) { MBAR_ARRIVE(dfrb); }
                            else           { MBAR_ARRIVE_CLUSTER0(dfrb); }
                        }
                    }
#pragma unroll
                    for (int q = 0; q < 8; q++) {
                        float4 bv = *reinterpret_cast<const float4*>(bias + c0 + q * 4);
                        float4 v;
                        v.x = __uint_as_float(r[q * 4 + 0]) + bv.x;
                        v.y = __uint_as_float(r[q * 4 + 1]) + bv.y;
                        v.z = __uint_as_float(r[q * 4 + 2]) + bv.z;
                        v.w = __uint_as_float(r[q * 4 + 3]) + bv.w;
                        *reinterpret_cast<float4*>(orow + c0 + q * 4) = v;
                    }
                }
            }
        }
    }

    __syncthreads();
    // Peer may still be MMA-reading our SMEM / arriving on our barriers.
    CLUSTER_SYNC();
    if (wid == 0) {
        asm volatile("tcgen05.dealloc.cta_group::2.sync.aligned.b32 %0, %1;"
                     :: "r"(tmem), "r"(512));
    }

#else
    // =================== SIMT fp32 fallback (non-'a' pass) ================
    (void)mx; (void)mh;
    extern __shared__ char smem_raw[];
    float* Xs = reinterpret_cast<float*>(smem_raw);          // [128][33]
    float* Hs = Xs + 128 * 33;                               // [64][33]

    int tid = threadIdx.x;
    int ty = tid >> 4, tx = tid & 15;

    for (int g = bid; g < ntiles; g += GRID) {
        int m0 = (g >> 1) * 256;
        int nb = g & 1;
        for (int half = 0; half < 2; half++) {
            int m0h = m0 + half * 128;
            for (int nc = 0; nc < 4; nc++) {
                int col0 = nb * 256 + nc * 64;
                float acc[8][4];
#pragma unroll
                for (int i = 0; i < 8; i++)
#pragma unroll
                    for (int j = 0; j < 4; j++) acc[i][j] = 0.f;

                for (int kb = 0; kb < 16; kb++) {
#pragma unroll
                    for (int it = 0; it < 16; it++) {
                        int idx = tid + it * 256;
                        int r = idx >> 5, k = idx & 31;
                        Xs[r * 33 + k] = x[(size_t)(m0h + r) * N_F + kb * 32 + k];
                    }
#pragma unroll
                    for (int it = 0; it < 8; it++) {
                        int idx = tid + it * 256;
                        int r = idx >> 5, k = idx & 31;
                        Hs[r * 33 + k] = g_H[(size_t)(col0 + r) * N_F + kb * 32 + k];
                    }
                    __syncthreads();
#pragma unroll
                    for (int k = 0; k < 32; k++) {
                        float a8[8], b4[4];
#pragma unroll
                        for (int i = 0; i < 8; i++) a8[i] = Xs[(ty * 8 + i) * 33 + k];
#pragma unroll
                        for (int j = 0; j < 4; j++) b4[j] = Hs[(tx * 4 + j) * 33 + k];
#pragma unroll
                        for (int i = 0; i < 8; i++)
#pragma unroll
                            for (int j = 0; j < 4; j++)
                                acc[i][j] = fmaf(a8[i], b4[j], acc[i][j]);
                    }
                    __syncthreads();
                }
#pragma unroll
                for (int i = 0; i < 8; i++)
#pragma unroll
                    for (int j = 0; j < 4; j++) {
                        int col = col0 + tx * 4 + j;
                        out[(size_t)(m0h + ty * 8 + i) * N_F + col] = acc[i][j] + bias[col];
                    }
            }
        }
    }
#endif
}

// ---------------------------------------------------------------------------
// Host launcher
// ---------------------------------------------------------------------------
typedef CUresult (*PFN_encodeTiled)(
    CUtensorMap*, CUtensorMapDataType, cuuint32_t, void*,
    const cuuint64_t*, const cuuint64_t*, const cuuint32_t*, const cuuint32_t*,
    CUtensorMapInterleave, CUtensorMapSwizzle, CUtensorMapL2promotion,
    CUtensorMapFloatOOBfill);

extern "C" void kernel_launch(void* const* d_in, const int* in_sizes, int n_in,
                              void* d_out, int out_size) {
    const float* x    = (const float*)d_in[0];
    const float* A    = (const float*)d_in[1];
    const float* S    = (const float*)d_in[2];
    const float* bias = (const float*)d_in[3];
    float* out = (float*)d_out;

    long Mrows = (long)in_sizes[0] / N_F;   // 131072
    int ntiles = (int)(Mrows / 256) * 2;    // fallback path only

    build_H<<<N_F, N_F>>>(A, S);

    void* hswptr = nullptr;
    cudaGetSymbolAddress(&hswptr, g_Hsw);

    // Resolve cuTensorMapEncodeTiled via the runtime (no -lcuda needed).
    PFN_encodeTiled enc = nullptr;
    {
        cudaDriverEntryPointQueryResult st;
        cudaGetDriverEntryPointByVersion("cuTensorMapEncodeTiled", (void**)&enc,
                                         12050, cudaEnableDefault, &st);
    }

    CUtensorMap mx{}, mh{};
    if (enc) {
        {
            // X: 3D [k=512][m=131072][1], box {32,128,1}, SW128
            cuuint64_t dims[3]    = {(cuuint64_t)N_F, (cuuint64_t)Mrows, 1};
            cuuint64_t strides[2] = {(cuuint64_t)N_F * 4, (cuuint64_t)N_F * 4 * Mrows};
            cuuint32_t box[3]     = {KC, 128, 1};
            cuuint32_t es[3]      = {1, 1, 1};
            enc(&mx, CU_TENSOR_MAP_DATA_TYPE_FLOAT32, 3, (void*)x,
                dims, strides, box, es,
                CU_TENSOR_MAP_INTERLEAVE_NONE, CU_TENSOR_MAP_SWIZZLE_128B,
                CU_TENSOR_MAP_L2_PROMOTION_L2_128B, CU_TENSOR_MAP_FLOAT_OOB_FILL_NONE);
        }
        {
            // H (pre-swizzled image): 2D [256 floats/row][1024 rows of 1024B],
            // box {256, 32} = one 32KB (kc,rank) segment, SWIZZLE_NONE.
            cuuint64_t dims[2]    = {256, 1024};
            cuuint64_t strides[1] = {1024};
            cuuint32_t box[2]     = {256, 32};
            cuuint32_t es[2]      = {1, 1};
            enc(&mh, CU_TENSOR_MAP_DATA_TYPE_FLOAT32, 2, hswptr,
                dims, strides, box, es,
                CU_TENSOR_MAP_INTERLEAVE_NONE, CU_TENSOR_MAP_SWIZZLE_NONE,
                CU_TENSOR_MAP_L2_PROMOTION_L2_128B, CU_TENSOR_MAP_FLOAT_OOB_FILL_NONE);
        }
    }

    cudaFuncSetAttribute(phm_gemm, cudaFuncAttributeMaxDynamicSharedMemorySize, SMEM_BYTES);
    phm_gemm<<<GRID, 256, SMEM_BYTES>>>(x, bias, out, ntiles, mx, mh);
}

// round 14
// speedup vs baseline: 1.0108x; 1.0108x over previous
#include <cuda_runtime.h>
#include <cuda.h>
#include <cstdint>

// ============================================================================
// PHM8Linear: out[131072,512] = X[131072,512] @ H[512,512]^T + bias
// H[a*64+b][c*64+d] = sum_i A[i,a,c] * S[i,b,d]
// tcgen05 TF32 cta_group::2 SS GEMM, persistent grid=148, cluster (2,1,1).
// R14: KC=64 per pipeline position (16 MMA dispatches, floor 2048 cyc) to
// amortize the measured ~1400-cyc fixed per-position pipeline cost.
// X: 2 SW128 sub-tiles (16KB each) per stage; H: 2 pre-swizzled 32KB
// segments per stage. Rings: X 3x32KB, H 2x64KB. Epilogue split per N-half
// with lookahead-2 D0 burst. X raw fp32 (HW tf32 truncate); H RN-rounded.
// ============================================================================

#define N_F    512
#define KC     64          // K elems per position (2 x SW128 rows)
#define NXS    3           // X ring depth
#define NHS    2           // H ring depth
#define GRID   148
#define NPAIR  74
#define M_TILES 512        // 131072/256
#define PPT    8           // positions per tile (512/KC)

__device__ float g_H[N_F * N_F];     // row-major H (SIMT fallback only)
__device__ float g_Hsw[N_F * N_F];   // pre-swizzled SW128 images: [kc32][rank][b][16KB]

#if defined(__CUDA_ARCH__) && (defined(__CUDA_ARCH_FEAT_SM103_ALL) || \
    defined(__CUDA_ARCH_FEAT_SM100_ALL) || defined(__CUDA_ARCH_FEAT_SM101_ALL))
#define HAS_TCGEN05 1
#else
#define HAS_TCGEN05 0
#endif

// ---------------- smem layout (dynamic), tcgen05 path ----------------
#define OFF_TPTR    0
#define OFF_XFULL(s) (8 + 8 * (s))       // 3
#define OFF_XDONE(s) (40 + 8 * (s))      // 3
#define OFF_HFULL(s) (72 + 8 * (s))      // 2
#define OFF_HDONE(s) (96 + 8 * (s))      // 2
#define OFF_EPI0    120
#define OFF_EPI1    128
#define OFF_DFREE0  136
#define OFF_DFREE1  144
#define OFF_XS(s)   (1024 + (s) * 32768)    // 3 x 32KB (sub0 16KB | sub1 16KB)
#define OFF_HS(s)   (99328 + (s) * 65536)   // 2 x 64KB (kcA: H0|H1, kcB: H0|H1)
#define SMEM_BYTES  230400
#define EXPECT_X    65536u    // 32KB x 2 CTAs onto leader's barrier
#define EXPECT_H    131072u   // 64KB x 2 CTAs

// idesc: kind::tf32, D=F32(1<<4), A=TF32(2<<7), B=TF32(2<<10), N=256, M=256
#define IDESC_TF32_CG2 ((1u << 4) | (2u << 7) | (2u << 10) | ((256u / 8u) << 17) | ((256u / 16u) << 24))

// K-major SW128 smem descriptor base: layout=SW128(2), version=1, SBO=64, LBO=1
static __device__ __host__ constexpr uint64_t DESC_BASE_SW128 =
    (uint64_t(2) << 61) | (uint64_t(1) << 46) | (uint64_t(64) << 32) | (uint64_t(1) << 16);

__device__ __forceinline__ uint32_t s2u(const void* p) {
    uint32_t a;
    asm("{ .reg .u64 t; cvta.to.shared.u64 t, %1; cvt.u32.u64 %0, t; }" : "=r"(a) : "l"(p));
    return a;
}

#define MBAR_INIT(addr, cnt) \
    asm volatile("mbarrier.init.shared.b64 [%0], %1;" :: "r"(addr), "r"(cnt) : "memory")

#define MBAR_ARRIVE(addr) \
    asm volatile("mbarrier.arrive.shared.b64 _, [%0];" :: "r"(addr) : "memory")

// Arrive on the same-offset mbarrier in cluster CTA rank 0.
#define MBAR_ARRIVE_CLUSTER0(addr)                                             \
    asm volatile("{\n\t.reg .b32 ra;\n\t"                                      \
        "mapa.shared::cluster.u32 ra, %0, %1;\n\t"                             \
        "mbarrier.arrive.shared::cluster.b64 _, [ra];\n\t}"                    \
        :: "r"(addr), "r"(0) : "memory")

#define MBAR_EXPECT_TX(addr, bytes) \
    asm volatile("mbarrier.arrive.expect_tx.shared.b64 _, [%0], %1;" :: "r"(addr), "r"(bytes) : "memory")

#define MBAR_WAIT_SCOPE(addr, parity, SCOPE) do {                              \
    uint32_t _mb = (addr); uint32_t _ph = (parity); uint32_t _dn;              \
    asm volatile("{\n\t.reg .pred p;\n\t"                                      \
        "mbarrier.try_wait.parity.acquire." SCOPE ".shared::cta.b64 p, [%1], %2;\n\t" \
        "selp.b32 %0, 1, 0, p;\n\t}" : "=r"(_dn) : "r"(_mb), "r"(_ph) : "memory"); \
    while (!_dn) {                                                             \
        asm volatile("{\n\t.reg .pred p;\n\t"                                  \
            "mbarrier.try_wait.parity.acquire." SCOPE ".shared::cta.b64 p, [%1], %2, 0x989680;\n\t" \
            "selp.b32 %0, 1, 0, p;\n\t}" : "=r"(_dn) : "r"(_mb), "r"(_ph) : "memory"); \
    }                                                                          \
} while (0)

#define MBAR_WAIT(addr, parity)     MBAR_WAIT_SCOPE(addr, parity, "cta")
#define MBAR_WAIT_CLU(addr, parity) MBAR_WAIT_SCOPE(addr, parity, "cluster")

// cta_group::2 TMA (3D): completes on leader's barrier (bit 24 cleared).
#define TMA3D_CG2(smem, map, cx, cy, cz, mbar)                                 \
    asm volatile("{\n\t.reg .b32 lb;\n\t"                                      \
        "and.b32 lb, %5, 0xFEFFFFFF;\n\t"                                      \
        "cp.async.bulk.tensor.3d.cta_group::2.shared::cluster.global"          \
        ".tile.mbarrier::complete_tx::bytes [%0], [%1, {%2, %3, %4}], [lb];\n\t}" \
        :: "r"(smem), "l"(map), "r"(cx), "r"(cy), "r"(cz), "r"(mbar) : "memory")

// cta_group::2 TMA (2D) — used for the pre-swizzled H fetch.
#define TMA2D_CG2(smem, map, cx, cy, mbar)                                     \
    asm volatile("{\n\t.reg .b32 lb;\n\t"                                      \
        "and.b32 lb, %4, 0xFEFFFFFF;\n\t"                                      \
        "cp.async.bulk.tensor.2d.cta_group::2.shared::cluster.global"          \
        ".tile.mbarrier::complete_tx::bytes [%0], [%1, {%2, %3}], [lb];\n\t}"  \
        :: "r"(smem), "l"(map), "r"(cx), "r"(cy), "r"(mbar) : "memory")

// cta_group::2 tf32 MMA (leader issues; A/B split across the CTA pair)
#define MMA_TF32_CG2(dst, adsc, bdsc, en)                                      \
    asm volatile("{\n\t.reg .pred p;\n\tsetp.ne.u32 p, %5, 0;\n\t"             \
        "tcgen05.mma.cta_group::2.kind::tf32 [%0], %1, %2, %3, "               \
        "{%4,%4,%4,%4,%4,%4,%4,%4}, p;\n\t}"                                   \
        :: "r"(dst), "l"(adsc), "l"(bdsc), "r"(IDESC_TF32_CG2), "r"(0u), "r"(en) : "memory")

#define TC_COMMIT_MC_CG2(mbar)                                                 \
    asm volatile("tcgen05.commit.cta_group::2.mbarrier::arrive::one.shared::cluster.multicast::cluster.b64 [%0], %1;" \
        :: "r"(mbar), "h"((uint16_t)3) : "memory")

#define CLUSTER_SYNC() do {                                                    \
    asm volatile("barrier.cluster.arrive.aligned;" ::: "memory");              \
    asm volatile("barrier.cluster.wait.aligned;" ::: "memory");                \
} while (0)

// ---------------------------------------------------------------------------
// H precompute: H[r=a*64+b][k=c*64+d] = sum_i A[i,a,c]*S[i,b,d], RN->tf32.
// g_Hsw: SW128 smem byte image, segmented [kc32][rank] (32KB each:
// block0 16KB | block1 16KB); linear TMA reproduces the swizzled image.
// ---------------------------------------------------------------------------
__global__ void build_H(const float* __restrict__ A, const float* __restrict__ S) {
    int r = blockIdx.x;     // 0..511
    int k = threadIdx.x;    // 0..511
    int a = r >> 6, bb = r & 63, c = k >> 6, d = k & 63;
    float acc = 0.f;
#pragma unroll
    for (int i = 0; i < 8; i++)
        acc = fmaf(A[i * 64 + a * 8 + c], S[i * 4096 + bb * 64 + d], acc);
    uint32_t t;
    asm("cvt.rna.tf32.f32 %0, %1;" : "=r"(t) : "f"(acc));
    float v = __uint_as_float(t);
    g_H[r * N_F + k] = v;

    int kc  = k >> 5;            // 32-wide k-chunk 0..15
    int col = k & 31;
    int b   = r >> 8;            // column block 0/1
    int rib = r & 255;
    int rr  = rib >> 7;          // rank half
    int row = rib & 127;
    uint32_t off = (uint32_t)(kc * 2 + rr) * 32768u + (uint32_t)b * 16384u;
    uint32_t bo  = (uint32_t)(row * 128 + col * 4);
    bo = bo ^ ((bo >> 3) & 0x70);            // SW128 swizzle
    *reinterpret_cast<float*>(reinterpret_cast<char*>(g_Hsw) + off + bo) = v;
}

// ---------------------------------------------------------------------------
// Main GEMM kernel
// ---------------------------------------------------------------------------
__global__ void __launch_bounds__(256, 1) __cluster_dims__(2, 1, 1) phm_gemm(
    const float* __restrict__ x,
    const float* __restrict__ bias, float* __restrict__ out,
    int ntiles,
    const __grid_constant__ CUtensorMap mx,
    const __grid_constant__ CUtensorMap mh)
{
    int bid = blockIdx.x;

#if HAS_TCGEN05
    // =================== tcgen05 TF32 cg2 path (sm_103a) ==================
    (void)x; (void)ntiles;
    extern __shared__ char smem_raw[];
    uint32_t sb = s2u(smem_raw);
    int tid = threadIdx.x, wid = tid >> 5, lid = tid & 31;

    int c    = bid >> 1;        // pair id (0..73)
    int rank = bid & 1;         // cluster rank
    int cnt  = 1 + (M_TILES - 1 - c) / NPAIR;   // tiles for this pair

    if (wid == 0) {
        asm volatile("tcgen05.alloc.cta_group::2.sync.aligned.shared::cta.b32 [%0], %1;"
                     :: "r"(sb + OFF_TPTR), "r"(512) : "memory");
        asm volatile("tcgen05.relinquish_alloc_permit.cta_group::2.sync.aligned;");
    }
    if (tid == 0) {
#pragma unroll
        for (int s = 0; s < NXS; s++) {
            MBAR_INIT(sb + OFF_XFULL(s), 1);
            MBAR_INIT(sb + OFF_XDONE(s), 1);
        }
#pragma unroll
        for (int s = 0; s < NHS; s++) {
            MBAR_INIT(sb + OFF_HFULL(s), 1);
            MBAR_INIT(sb + OFF_HDONE(s), 1);
        }
        MBAR_INIT(sb + OFF_EPI0, 1);
        MBAR_INIT(sb + OFF_EPI1, 1);
        MBAR_INIT(sb + OFF_DFREE0, 12);      // 6 epilogue warps x 2 CTAs
        MBAR_INIT(sb + OFF_DFREE1, 12);
    }
    __syncthreads();
    uint32_t tmem;
    asm volatile("ld.shared.b32 %0, [%1];" : "=r"(tmem) : "r"(sb + OFF_TPTR));

    // All mbarriers live in both CTAs before any cross-CTA TMA/commit.
    CLUSTER_SYNC();

    if (wid == 0 && lid == 0 && rank == 0) {
        // ---------------- MMA dispatcher (leader only) ----------------
        // X stage: sub0 @+0, sub1 @+16KB. H stage: kcA H0 @+0, kcA H1 @+16KB,
        // kcB H0 @+32KB, kcB H1 @+48KB. Desc units = 16B (+16KB = +1024).
        uint64_t dX[NXS], dH[NHS];
#pragma unroll
        for (int s = 0; s < NXS; s++)
            dX[s] = DESC_BASE_SW128 | (((sb + OFF_XS(s)) >> 4) & 0x3FFF);
#pragma unroll
        for (int s = 0; s < NHS; s++)
            dH[s] = DESC_BASE_SW128 | (((sb + OFF_HS(s)) >> 4) & 0x3FFF);

        int xs = 0, xph = 0, hs = 0, hph = 0;
        for (int j = 0; j < cnt; j++) {
            int sx[2], sh[2];
            // ---- phase A: positions 0..1, D0 MMAs (overlap epilogue D1 read)
            if (j > 0) {
                MBAR_WAIT(sb + OFF_DFREE0, (j - 1) & 1);
                asm volatile("tcgen05.fence::after_thread_sync;" ::: "memory");
            }
#pragma unroll
            for (int q = 0; q < 2; q++) {
                MBAR_WAIT_CLU(sb + OFF_XFULL(xs), xph);
                MBAR_WAIT_CLU(sb + OFF_HFULL(hs), hph);
#pragma unroll
                for (int ks = 0; ks < 4; ks++)
                    MMA_TF32_CG2(tmem, dX[xs] + 2 * ks, dH[hs] + 2 * ks, (q | ks) ? 1u : 0u);
#pragma unroll
                for (int ks = 0; ks < 4; ks++)
                    MMA_TF32_CG2(tmem, dX[xs] + 1024 + 2 * ks, dH[hs] + 2048 + 2 * ks, 1u);
                sx[q] = xs; sh[q] = hs;
                if (++xs == NXS) { xs = 0; xph ^= 1; }
                if (++hs == NHS) { hs = 0; hph ^= 1; }
            }
            // ---- phase B: D1 for positions 0..1 + done commits
            if (j > 0) {
                MBAR_WAIT(sb + OFF_DFREE1, (j - 1) & 1);
                asm volatile("tcgen05.fence::after_thread_sync;" ::: "memory");
            }
#pragma unroll
            for (int q = 0; q < 2; q++) {
#pragma unroll
                for (int ks = 0; ks < 4; ks++)
                    MMA_TF32_CG2(tmem + 256, dX[sx[q]] + 2 * ks, dH[sh[q]] + 1024 + 2 * ks, (q | ks) ? 1u : 0u);
#pragma unroll
                for (int ks = 0; ks < 4; ks++)
                    MMA_TF32_CG2(tmem + 256, dX[sx[q]] + 1024 + 2 * ks, dH[sh[q]] + 3072 + 2 * ks, 1u);
                TC_COMMIT_MC_CG2(sb + OFF_XDONE(sx[q]));
                TC_COMMIT_MC_CG2(sb + OFF_HDONE(sh[q]));
            }
            // ---- steady positions 2..7
            for (int p = 2; p < PPT; p++) {
                MBAR_WAIT_CLU(sb + OFF_XFULL(xs), xph);
                MBAR_WAIT_CLU(sb + OFF_HFULL(hs), hph);
#pragma unroll
                for (int ks = 0; ks < 4; ks++)
                    MMA_TF32_CG2(tmem, dX[xs] + 2 * ks, dH[hs] + 2 * ks, 1u);
#pragma unroll
                for (int ks = 0; ks < 4; ks++)
                    MMA_TF32_CG2(tmem, dX[xs] + 1024 + 2 * ks, dH[hs] + 2048 + 2 * ks, 1u);
                if (p == PPT - 1) TC_COMMIT_MC_CG2(sb + OFF_EPI0);   // D0 final
#pragma unroll
                for (int ks = 0; ks < 4; ks++)
                    MMA_TF32_CG2(tmem + 256, dX[xs] + 2 * ks, dH[hs] + 1024 + 2 * ks, 1u);
#pragma unroll
                for (int ks = 0; ks < 4; ks++)
                    MMA_TF32_CG2(tmem + 256, dX[xs] + 1024 + 2 * ks, dH[hs] + 3072 + 2 * ks, 1u);
                TC_COMMIT_MC_CG2(sb + OFF_XDONE(xs));
                TC_COMMIT_MC_CG2(sb + OFF_HDONE(hs));
                if (p == PPT - 1) TC_COMMIT_MC_CG2(sb + OFF_EPI1);   // D1 final
                if (++xs == NXS) { xs = 0; xph ^= 1; }
                if (++hs == NHS) { hs = 0; hph ^= 1; }
            }
        }
    } else if (wid == 1 && lid == 0) {
        // ---------------- TMA producer (both ranks) ----------------
        int xs = 0, xph = 0, hs = 0, hph = 0;
        int filled = 0;
        for (int j = 0; j < cnt; j++) {
            int m0 = (c + NPAIR * j) * 256;
            for (int k = 0; k < PPT; k++) {
                // X fill: 2 SW128 sub-tiles (k*64 and k*64+32)
                if (filled >= NXS)
                    MBAR_WAIT(sb + OFF_XDONE(xs), xph ^ 1);
                if (rank == 0)
                    MBAR_EXPECT_TX(sb + OFF_XFULL(xs), EXPECT_X);
                TMA3D_CG2(sb + OFF_XS(xs),         &mx, k * KC,      m0 + rank * 128, 0,
                          sb + OFF_XFULL(xs));
                TMA3D_CG2(sb + OFF_XS(xs) + 16384, &mx, k * KC + 32, m0 + rank * 128, 0,
                          sb + OFF_XFULL(xs));
                // H fill: 2 pre-swizzled 32KB segments (kc32 = 2k, 2k+1)
                if (filled >= NHS)
                    MBAR_WAIT(sb + OFF_HDONE(hs), hph ^ 1);
                if (rank == 0)
                    MBAR_EXPECT_TX(sb + OFF_HFULL(hs), EXPECT_H);
                TMA2D_CG2(sb + OFF_HS(hs),         &mh, 0, (4 * k + rank) * 32,
                          sb + OFF_HFULL(hs));
                TMA2D_CG2(sb + OFF_HS(hs) + 32768, &mh, 0, (4 * k + 2 + rank) * 32,
                          sb + OFF_HFULL(hs));
                filled++;
                if (++xs == NXS) { xs = 0; xph ^= 1; }
                if (++hs == NHS) { hs = 0; hph ^= 1; }
            }
        }
    } else if (wid >= 2) {
        // ---------------- epilogue warps (2..7, both ranks) ----------------
        // Per half (256 cols = 8 chunks): sp0=warp4 (8), sp1=warp5 (8),
        // sp2=warps2/6 (4+4), sp3=warps3/7 (4+4).
        int sp = wid & 3;
        int nch = (sp < 2) ? 8 : 4;
        int ch0 = (sp < 2) ? 0 : ((wid >= 6) ? 4 : 0);
        for (int j = 0; j < cnt; j++) {
            size_t row = (size_t)((c + NPAIR * j) * 256 + rank * 128 + sp * 32 + lid);
            float* orow = out + row * N_F;
#pragma unroll
            for (int half = 0; half < 2; half++) {
                MBAR_WAIT(sb + (half ? OFF_EPI1 : OFF_EPI0), j & 1);
                asm volatile("tcgen05.fence::after_thread_sync;" ::: "memory");
                for (int cc = 0; cc < nch; cc++) {
                    int c0 = half * 256 + (ch0 + cc) * 32;
                    uint32_t r[32];
                    asm volatile(
                        "tcgen05.ld.sync.aligned.32x32b.x32.b32 "
                        "{%0, %1, %2, %3, %4, %5, %6, %7, "
                        " %8, %9, %10, %11, %12, %13, %14, %15, "
                        " %16, %17, %18, %19, %20, %21, %22, %23, "
                        " %24, %25, %26, %27, %28, %29, %30, %31}, [%32];"
                        : "=r"(r[0]),  "=r"(r[1]),  "=r"(r[2]),  "=r"(r[3]),
                          "=r"(r[4]),  "=r"(r[5]),  "=r"(r[6]),  "=r"(r[7]),
                          "=r"(r[8]),  "=r"(r[9]),  "=r"(r[10]), "=r"(r[11]),
                          "=r"(r[12]), "=r"(r[13]), "=r"(r[14]), "=r"(r[15]),
                          "=r"(r[16]), "=r"(r[17]), "=r"(r[18]), "=r"(r[19]),
                          "=r"(r[20]), "=r"(r[21]), "=r"(r[22]), "=r"(r[23]),
                          "=r"(r[24]), "=r"(r[25]), "=r"(r[26]), "=r"(r[27]),
                          "=r"(r[28]), "=r"(r[29]), "=r"(r[30]), "=r"(r[31])
                        : "r"(tmem + c0));
                    asm volatile("tcgen05.wait::ld.sync.aligned;" ::: "memory");
                    if (cc == nch - 1) {
                        // this half's D cols read into regs -> release dispatcher
                        asm volatile("tcgen05.fence::before_thread_sync;" ::: "memory");
                        if (lid == 0) {
                            uint32_t dfrb = sb + (half ? OFF_DFREE1 : OFF_DFREE0);
                            if (rank == 0) { MBAR_ARRIVE(dfrb); }
                            else           { MBAR_ARRIVE_CLUSTER0(dfrb); }
                        }
                    }
#pragma unroll
                    for (int q = 0; q < 8; q++) {
                        float4 bv = *reinterpret_cast<const float4*>(bias + c0 + q * 4);
                        float4 v;
                        v.x = __uint_as_float(r[q * 4 + 0]) + bv.x;
                        v.y = __uint_as_float(r[q * 4 + 1]) + bv.y;
                        v.z = __uint_as_float(r[q * 4 + 2]) + bv.z;
                        v.w = __uint_as_float(r[q * 4 + 3]) + bv.w;
                        *reinterpret_cast<float4*>(orow + c0 + q * 4) = v;
                    }
                }
            }
        }
    }

    __syncthreads();
    // Peer may still be MMA-reading our SMEM / arriving on our barriers.
    CLUSTER_SYNC();
    if (wid == 0) {
        asm volatile("tcgen05.dealloc.cta_group::2.sync.aligned.b32 %0, %1;"
                     :: "r"(tmem), "r"(512));
    }

#else
    // =================== SIMT fp32 fallback (non-'a' pass) ================
    (void)mx; (void)mh;
    extern __shared__ char smem_raw[];
    float* Xs = reinterpret_cast<float*>(smem_raw);          // [128][33]
    float* Hs = Xs + 128 * 33;                               // [64][33]

    int tid = threadIdx.x;
    int ty = tid >> 4, tx = tid & 15;

    for (int g = bid; g < ntiles; g += GRID) {
        int m0 = (g >> 1) * 256;
        int nb = g & 1;
        for (int half = 0; half < 2; half++) {
            int m0h = m0 + half * 128;
            for (int nc = 0; nc < 4; nc++) {
                int col0 = nb * 256 + nc * 64;
                float acc[8][4];
#pragma unroll
                for (int i = 0; i < 8; i++)
#pragma unroll
                    for (int j = 0; j < 4; j++) acc[i][j] = 0.f;

                for (int kb = 0; kb < 16; kb++) {
#pragma unroll
                    for (int it = 0; it < 16; it++) {
                        int idx = tid + it * 256;
                        int r = idx >> 5, k = idx & 31;
                        Xs[r * 33 + k] = x[(size_t)(m0h + r) * N_F + kb * 32 + k];
                    }
#pragma unroll
                    for (int it = 0; it < 8; it++) {
                        int idx = tid + it * 256;
                        int r = idx >> 5, k = idx & 31;
                        Hs[r * 33 + k] = g_H[(size_t)(col0 + r) * N_F + kb * 32 + k];
                    }
                    __syncthreads();
#pragma unroll
                    for (int k = 0; k < 32; k++) {
                        float a8[8], b4[4];
#pragma unroll
                        for (int i = 0; i < 8; i++) a8[i] = Xs[(ty * 8 + i) * 33 + k];
#pragma unroll
                        for (int j = 0; j < 4; j++) b4[j] = Hs[(tx * 4 + j) * 33 + k];
#pragma unroll
                        for (int i = 0; i < 8; i++)
#pragma unroll
                            for (int j = 0; j < 4; j++)
                                acc[i][j] = fmaf(a8[i], b4[j], acc[i][j]);
                    }
                    __syncthreads();
                }
#pragma unroll
                for (int i = 0; i < 8; i++)
#pragma unroll
                    for (int j = 0; j < 4; j++) {
                        int col = col0 + tx * 4 + j;
                        out[(size_t)(m0h + ty * 8 + i) * N_F + col] = acc[i][j] + bias[col];
                    }
            }
        }
    }
#endif
}

// ---------------------------------------------------------------------------
// Host launcher
// ---------------------------------------------------------------------------
typedef CUresult (*PFN_encodeTiled)(
    CUtensorMap*, CUtensorMapDataType, cuuint32_t, void*,
    const cuuint64_t*, const cuuint64_t*, const cuuint32_t*, const cuuint32_t*,
    CUtensorMapInterleave, CUtensorMapSwizzle, CUtensorMapL2promotion,
    CUtensorMapFloatOOBfill);

extern "C" void kernel_launch(void* const* d_in, const int* in_sizes, int n_in,
                              void* d_out, int out_size) {
    const float* x    = (const float*)d_in[0];
    const float* A    = (const float*)d_in[1];
    const float* S    = (const float*)d_in[2];
    const float* bias = (const float*)d_in[3];
    float* out = (float*)d_out;

    long Mrows = (long)in_sizes[0] / N_F;   // 131072
    int ntiles = (int)(Mrows / 256) * 2;    // fallback path only

    build_H<<<N_F, N_F>>>(A, S);

    void* hswptr = nullptr;
    cudaGetSymbolAddress(&hswptr, g_Hsw);

    // Resolve cuTensorMapEncodeTiled via the runtime (no -lcuda needed).
    PFN_encodeTiled enc = nullptr;
    {
        cudaDriverEntryPointQueryResult st;
        cudaGetDriverEntryPointByVersion("cuTensorMapEncodeTiled", (void**)&enc,
                                         12050, cudaEnableDefault, &st);
    }

    CUtensorMap mx{}, mh{};
    if (enc) {
        {
            // X: 3D [k=512][m=131072][1], box {32,128,1}, SW128
            cuuint64_t dims[3]    = {(cuuint64_t)N_F, (cuuint64_t)Mrows, 1};
            cuuint64_t strides[2] = {(cuuint64_t)N_F * 4, (cuuint64_t)N_F * 4 * Mrows};
            cuuint32_t box[3]     = {32, 128, 1};
            cuuint32_t es[3]      = {1, 1, 1};
            enc(&mx, CU_TENSOR_MAP_DATA_TYPE_FLOAT32, 3, (void*)x,
                dims, strides, box, es,
                CU_TENSOR_MAP_INTERLEAVE_NONE, CU_TENSOR_MAP_SWIZZLE_128B,
                CU_TENSOR_MAP_L2_PROMOTION_L2_128B, CU_TENSOR_MAP_FLOAT_OOB_FILL_NONE);
        }
        {
            // H (pre-swizzled image): 2D [256 floats/row][1024 rows of 1024B],
            // box {256, 32} = one 32KB (kc32,rank) segment, SWIZZLE_NONE.
            cuuint64_t dims[2]    = {256, 1024};
            cuuint64_t strides[1] = {1024};
            cuuint32_t box[2]     = {256, 32};
            cuuint32_t es[2]      = {1, 1};
            enc(&mh, CU_TENSOR_MAP_DATA_TYPE_FLOAT32, 2, hswptr,
                dims, strides, box, es,
                CU_TENSOR_MAP_INTERLEAVE_NONE, CU_TENSOR_MAP_SWIZZLE_NONE,
                CU_TENSOR_MAP_L2_PROMOTION_L2_128B, CU_TENSOR_MAP_FLOAT_OOB_FILL_NONE);
        }
    }

    cudaFuncSetAttribute(phm_gemm, cudaFuncAttributeMaxDynamicSharedMemorySize, SMEM_BYTES);
    phm_gemm<<<GRID, 256, SMEM_BYTES>>>(x, bias, out, ntiles, mx, mh);
}

// round 15
// speedup vs baseline: 1.0549x; 1.0437x over previous
#include <cuda_runtime.h>
#include <cuda.h>
#include <cstdint>

// ============================================================================
// PHM8Linear: out[131072,512] = X[131072,512] @ H[512,512]^T + bias
// H[a*64+b][c*64+d] = sum_i A[i,a,c] * S[i,b,d]
// tcgen05 TF32 cta_group::2 SS GEMM, persistent grid=148, cluster (2,1,1).
// R15: epilogue parallelized — 320 threads, 8 epilogue warps (2 per TMEM
// subpartition, 4 chunks each), ping-pong LDTM/STG pipeline, bias cached in
// smem. Mainloop = r14 (KC=64/position, X ring 3x32KB, H ring 2x64KB,
// pre-swizzled H images, epilogue split per N-half with lookahead-2 burst).
// X raw fp32 (HW tf32 truncate); H RN-rounded in build_H.
// ============================================================================

#define N_F    512
#define KC     64          // K elems per position (2 x SW128 rows)
#define NXS    3           // X ring depth
#define NHS    2           // H ring depth
#define GRID   148
#define NPAIR  74
#define M_TILES 512        // 131072/256
#define PPT    8           // positions per tile (512/KC)
#define NTHREADS 320

__device__ float g_H[N_F * N_F];     // row-major H (SIMT fallback only)
__device__ float g_Hsw[N_F * N_F];   // pre-swizzled SW128 images: [kc32][rank][b][16KB]

#if defined(__CUDA_ARCH__) && (defined(__CUDA_ARCH_FEAT_SM103_ALL) || \
    defined(__CUDA_ARCH_FEAT_SM100_ALL) || defined(__CUDA_ARCH_FEAT_SM101_ALL))
#define HAS_TCGEN05 1
#else
#define HAS_TCGEN05 0
#endif

// ---------------- smem layout (dynamic), tcgen05 path ----------------
#define OFF_TPTR    0
#define OFF_XFULL(s) (8 + 8 * (s))       // 3
#define OFF_XDONE(s) (40 + 8 * (s))      // 3
#define OFF_HFULL(s) (72 + 8 * (s))      // 2
#define OFF_HDONE(s) (96 + 8 * (s))      // 2
#define OFF_EPI0    120
#define OFF_EPI1    128
#define OFF_DFREE0  136
#define OFF_DFREE1  144
#define OFF_BIAS    256                      // 512 floats = 2KB (cached bias)
#define OFF_XS(s)   (3072 + (s) * 32768)     // 3 x 32KB (sub0 16KB | sub1 16KB)
#define OFF_HS(s)   (101376 + (s) * 65536)   // 2 x 64KB (kcA H0|H1, kcB H0|H1)
#define SMEM_BYTES  232448                   // 227KB opt-in max
#define EXPECT_X    65536u    // 32KB x 2 CTAs onto leader's barrier
#define EXPECT_H    131072u   // 64KB x 2 CTAs

// idesc: kind::tf32, D=F32(1<<4), A=TF32(2<<7), B=TF32(2<<10), N=256, M=256
#define IDESC_TF32_CG2 ((1u << 4) | (2u << 7) | (2u << 10) | ((256u / 8u) << 17) | ((256u / 16u) << 24))

// K-major SW128 smem descriptor base: layout=SW128(2), version=1, SBO=64, LBO=1
static __device__ __host__ constexpr uint64_t DESC_BASE_SW128 =
    (uint64_t(2) << 61) | (uint64_t(1) << 46) | (uint64_t(64) << 32) | (uint64_t(1) << 16);

__device__ __forceinline__ uint32_t s2u(const void* p) {
    uint32_t a;
    asm("{ .reg .u64 t; cvta.to.shared.u64 t, %1; cvt.u32.u64 %0, t; }" : "=r"(a) : "l"(p));
    return a;
}

#define MBAR_INIT(addr, cnt) \
    asm volatile("mbarrier.init.shared.b64 [%0], %1;" :: "r"(addr), "r"(cnt) : "memory")

#define MBAR_ARRIVE(addr) \
    asm volatile("mbarrier.arrive.shared.b64 _, [%0];" :: "r"(addr) : "memory")

// Arrive on the same-offset mbarrier in cluster CTA rank 0.
#define MBAR_ARRIVE_CLUSTER0(addr)                                             \
    asm volatile("{\n\t.reg .b32 ra;\n\t"                                      \
        "mapa.shared::cluster.u32 ra, %0, %1;\n\t"                             \
        "mbarrier.arrive.shared::cluster.b64 _, [ra];\n\t}"                    \
        :: "r"(addr), "r"(0) : "memory")

#define MBAR_EXPECT_TX(addr, bytes) \
    asm volatile("mbarrier.arrive.expect_tx.shared.b64 _, [%0], %1;" :: "r"(addr), "r"(bytes) : "memory")

#define MBAR_WAIT_SCOPE(addr, parity, SCOPE) do {                              \
    uint32_t _mb = (addr); uint32_t _ph = (parity); uint32_t _dn;              \
    asm volatile("{\n\t.reg .pred p;\n\t"                                      \
        "mbarrier.try_wait.parity.acquire." SCOPE ".shared::cta.b64 p, [%1], %2;\n\t" \
        "selp.b32 %0, 1, 0, p;\n\t}" : "=r"(_dn) : "r"(_mb), "r"(_ph) : "memory"); \
    while (!_dn) {                                                             \
        asm volatile("{\n\t.reg .pred p;\n\t"                                  \
            "mbarrier.try_wait.parity.acquire." SCOPE ".shared::cta.b64 p, [%1], %2, 0x989680;\n\t" \
            "selp.b32 %0, 1, 0, p;\n\t}" : "=r"(_dn) : "r"(_mb), "r"(_ph) : "memory"); \
    }                                                                          \
} while (0)

#define MBAR_WAIT(addr, parity)     MBAR_WAIT_SCOPE(addr, parity, "cta")
#define MBAR_WAIT_CLU(addr, parity) MBAR_WAIT_SCOPE(addr, parity, "cluster")

// cta_group::2 TMA (3D): completes on leader's barrier (bit 24 cleared).
#define TMA3D_CG2(smem, map, cx, cy, cz, mbar)                                 \
    asm volatile("{\n\t.reg .b32 lb;\n\t"                                      \
        "and.b32 lb, %5, 0xFEFFFFFF;\n\t"                                      \
        "cp.async.bulk.tensor.3d.cta_group::2.shared::cluster.global"          \
        ".tile.mbarrier::complete_tx::bytes [%0], [%1, {%2, %3, %4}], [lb];\n\t}" \
        :: "r"(smem), "l"(map), "r"(cx), "r"(cy), "r"(cz), "r"(mbar) : "memory")

// cta_group::2 TMA (2D) — used for the pre-swizzled H fetch.
#define TMA2D_CG2(smem, map, cx, cy, mbar)                                     \
    asm volatile("{\n\t.reg .b32 lb;\n\t"                                      \
        "and.b32 lb, %4, 0xFEFFFFFF;\n\t"                                      \
        "cp.async.bulk.tensor.2d.cta_group::2.shared::cluster.global"          \
        ".tile.mbarrier::complete_tx::bytes [%0], [%1, {%2, %3}], [lb];\n\t}"  \
        :: "r"(smem), "l"(map), "r"(cx), "r"(cy), "r"(mbar) : "memory")

// cta_group::2 tf32 MMA (leader issues; A/B split across the CTA pair)
#define MMA_TF32_CG2(dst, adsc, bdsc, en)                                      \
    asm volatile("{\n\t.reg .pred p;\n\tsetp.ne.u32 p, %5, 0;\n\t"             \
        "tcgen05.mma.cta_group::2.kind::tf32 [%0], %1, %2, %3, "               \
        "{%4,%4,%4,%4,%4,%4,%4,%4}, p;\n\t}"                                   \
        :: "r"(dst), "l"(adsc), "l"(bdsc), "r"(IDESC_TF32_CG2), "r"(0u), "r"(en) : "memory")

#define TC_COMMIT_MC_CG2(mbar)                                                 \
    asm volatile("tcgen05.commit.cta_group::2.mbarrier::arrive::one.shared::cluster.multicast::cluster.b64 [%0], %1;" \
        :: "r"(mbar), "h"((uint16_t)3) : "memory")

#define CLUSTER_SYNC() do {                                                    \
    asm volatile("barrier.cluster.arrive.aligned;" ::: "memory");              \
    asm volatile("barrier.cluster.wait.aligned;" ::: "memory");                \
} while (0)

#define LDTM_X32(r, tmem_addr)                                                 \
    asm volatile(                                                              \
        "tcgen05.ld.sync.aligned.32x32b.x32.b32 "                              \
        "{%0, %1, %2, %3, %4, %5, %6, %7, "                                    \
        " %8, %9, %10, %11, %12, %13, %14, %15, "                              \
        " %16, %17, %18, %19, %20, %21, %22, %23, "                            \
        " %24, %25, %26, %27, %28, %29, %30, %31}, [%32];"                     \
        : "=r"((r)[0]),  "=r"((r)[1]),  "=r"((r)[2]),  "=r"((r)[3]),           \
          "=r"((r)[4]),  "=r"((r)[5]),  "=r"((r)[6]),  "=r"((r)[7]),           \
          "=r"((r)[8]),  "=r"((r)[9]),  "=r"((r)[10]), "=r"((r)[11]),          \
          "=r"((r)[12]), "=r"((r)[13]), "=r"((r)[14]), "=r"((r)[15]),          \
          "=r"((r)[16]), "=r"((r)[17]), "=r"((r)[18]), "=r"((r)[19]),          \
          "=r"((r)[20]), "=r"((r)[21]), "=r"((r)[22]), "=r"((r)[23]),          \
          "=r"((r)[24]), "=r"((r)[25]), "=r"((r)[26]), "=r"((r)[27]),          \
          "=r"((r)[28]), "=r"((r)[29]), "=r"((r)[30]), "=r"((r)[31])           \
        : "r"(tmem_addr))

// ---------------------------------------------------------------------------
// H precompute: H[r=a*64+b][k=c*64+d] = sum_i A[i,a,c]*S[i,b,d], RN->tf32.
// g_Hsw: SW128 smem byte image, segmented [kc32][rank] (32KB each:
// block0 16KB | block1 16KB); linear TMA reproduces the swizzled image.
// ---------------------------------------------------------------------------
__global__ void build_H(const float* __restrict__ A, const float* __restrict__ S) {
    int r = blockIdx.x;     // 0..511
    int k = threadIdx.x;    // 0..511
    int a = r >> 6, bb = r & 63, c = k >> 6, d = k & 63;
    float acc = 0.f;
#pragma unroll
    for (int i = 0; i < 8; i++)
        acc = fmaf(A[i * 64 + a * 8 + c], S[i * 4096 + bb * 64 + d], acc);
    uint32_t t;
    asm("cvt.rna.tf32.f32 %0, %1;" : "=r"(t) : "f"(acc));
    float v = __uint_as_float(t);
    g_H[r * N_F + k] = v;

    int kc  = k >> 5;            // 32-wide k-chunk 0..15
    int col = k & 31;
    int b   = r >> 8;            // column block 0/1
    int rib = r & 255;
    int rr  = rib >> 7;          // rank half
    int row = rib & 127;
    uint32_t off = (uint32_t)(kc * 2 + rr) * 32768u + (uint32_t)b * 16384u;
    uint32_t bo  = (uint32_t)(row * 128 + col * 4);
    bo = bo ^ ((bo >> 3) & 0x70);            // SW128 swizzle
    *reinterpret_cast<float*>(reinterpret_cast<char*>(g_Hsw) + off + bo) = v;
}

// ---------------------------------------------------------------------------
// Main GEMM kernel
// ---------------------------------------------------------------------------
__global__ void __launch_bounds__(NTHREADS, 1) __cluster_dims__(2, 1, 1) phm_gemm(
    const float* __restrict__ x,
    const float* __restrict__ bias, float* __restrict__ out,
    int ntiles,
    const __grid_constant__ CUtensorMap mx,
    const __grid_constant__ CUtensorMap mh)
{
    int bid = blockIdx.x;

#if HAS_TCGEN05
    // =================== tcgen05 TF32 cg2 path (sm_103a) ==================
    (void)x; (void)ntiles;
    extern __shared__ char smem_raw[];
    uint32_t sb = s2u(smem_raw);
    int tid = threadIdx.x, wid = tid >> 5, lid = tid & 31;

    int c    = bid >> 1;        // pair id (0..73)
    int rank = bid & 1;         // cluster rank
    int cnt  = 1 + (M_TILES - 1 - c) / NPAIR;   // tiles for this pair

    if (wid == 0) {
        asm volatile("tcgen05.alloc.cta_group::2.sync.aligned.shared::cta.b32 [%0], %1;"
                     :: "r"(sb + OFF_TPTR), "r"(512) : "memory");
        asm volatile("tcgen05.relinquish_alloc_permit.cta_group::2.sync.aligned;");
    }
    if (tid == 0) {
#pragma unroll
        for (int s = 0; s < NXS; s++) {
            MBAR_INIT(sb + OFF_XFULL(s), 1);
            MBAR_INIT(sb + OFF_XDONE(s), 1);
        }
#pragma unroll
        for (int s = 0; s < NHS; s++) {
            MBAR_INIT(sb + OFF_HFULL(s), 1);
            MBAR_INIT(sb + OFF_HDONE(s), 1);
        }
        MBAR_INIT(sb + OFF_EPI0, 1);
        MBAR_INIT(sb + OFF_EPI1, 1);
        MBAR_INIT(sb + OFF_DFREE0, 16);      // 8 epilogue warps x 2 CTAs
        MBAR_INIT(sb + OFF_DFREE1, 16);
    }
    // Cache bias in smem (512 floats)
    if (tid < 128)
        reinterpret_cast<float4*>(smem_raw + OFF_BIAS)[tid] =
            reinterpret_cast<const float4*>(bias)[tid];
    __syncthreads();
    uint32_t tmem;
    asm volatile("ld.shared.b32 %0, [%1];" : "=r"(tmem) : "r"(sb + OFF_TPTR));

    // All mbarriers live in both CTAs before any cross-CTA TMA/commit.
    CLUSTER_SYNC();

    if (wid == 0 && lid == 0 && rank == 0) {
        // ---------------- MMA dispatcher (leader only) ----------------
        uint64_t dX[NXS], dH[NHS];
#pragma unroll
        for (int s = 0; s < NXS; s++)
            dX[s] = DESC_BASE_SW128 | (((sb + OFF_XS(s)) >> 4) & 0x3FFF);
#pragma unroll
        for (int s = 0; s < NHS; s++)
            dH[s] = DESC_BASE_SW128 | (((sb + OFF_HS(s)) >> 4) & 0x3FFF);

        int xs = 0, xph = 0, hs = 0, hph = 0;
        for (int j = 0; j < cnt; j++) {
            int sx[2], sh[2];
            // ---- phase A: positions 0..1, D0 MMAs (overlap epilogue D1 read)
            if (j > 0) {
                MBAR_WAIT(sb + OFF_DFREE0, (j - 1) & 1);
                asm volatile("tcgen05.fence::after_thread_sync;" ::: "memory");
            }
#pragma unroll
            for (int q = 0; q < 2; q++) {
                MBAR_WAIT_CLU(sb + OFF_XFULL(xs), xph);
                MBAR_WAIT_CLU(sb + OFF_HFULL(hs), hph);
#pragma unroll
                for (int ks = 0; ks < 4; ks++)
                    MMA_TF32_CG2(tmem, dX[xs] + 2 * ks, dH[hs] + 2 * ks, (q | ks) ? 1u : 0u);
#pragma unroll
                for (int ks = 0; ks < 4; ks++)
                    MMA_TF32_CG2(tmem, dX[xs] + 1024 + 2 * ks, dH[hs] + 2048 + 2 * ks, 1u);
                sx[q] = xs; sh[q] = hs;
                if (++xs == NXS) { xs = 0; xph ^= 1; }
                if (++hs == NHS) { hs = 0; hph ^= 1; }
            }
            // ---- phase B: D1 for positions 0..1 + done commits
            if (j > 0) {
                MBAR_WAIT(sb + OFF_DFREE1, (j - 1) & 1);
                asm volatile("tcgen05.fence::after_thread_sync;" ::: "memory");
            }
#pragma unroll
            for (int q = 0; q < 2; q++) {
#pragma unroll
                for (int ks = 0; ks < 4; ks++)
                    MMA_TF32_CG2(tmem + 256, dX[sx[q]] + 2 * ks, dH[sh[q]] + 1024 + 2 * ks, (q | ks) ? 1u : 0u);
#pragma unroll
                for (int ks = 0; ks < 4; ks++)
                    MMA_TF32_CG2(tmem + 256, dX[sx[q]] + 1024 + 2 * ks, dH[sh[q]] + 3072 + 2 * ks, 1u);
                TC_COMMIT_MC_CG2(sb + OFF_XDONE(sx[q]));
                TC_COMMIT_MC_CG2(sb + OFF_HDONE(sh[q]));
            }
            // ---- steady positions 2..7
            for (int p = 2; p < PPT; p++) {
                MBAR_WAIT_CLU(sb + OFF_XFULL(xs), xph);
                MBAR_WAIT_CLU(sb + OFF_HFULL(hs), hph);
#pragma unroll
                for (int ks = 0; ks < 4; ks++)
                    MMA_TF32_CG2(tmem, dX[xs] + 2 * ks, dH[hs] + 2 * ks, 1u);
#pragma unroll
                for (int ks = 0; ks < 4; ks++)
                    MMA_TF32_CG2(tmem, dX[xs] + 1024 + 2 * ks, dH[hs] + 2048 + 2 * ks, 1u);
                if (p == PPT - 1) TC_COMMIT_MC_CG2(sb + OFF_EPI0);   // D0 final
#pragma unroll
                for (int ks = 0; ks < 4; ks++)
                    MMA_TF32_CG2(tmem + 256, dX[xs] + 2 * ks, dH[hs] + 1024 + 2 * ks, 1u);
#pragma unroll
                for (int ks = 0; ks < 4; ks++)
                    MMA_TF32_CG2(tmem + 256, dX[xs] + 1024 + 2 * ks, dH[hs] + 3072 + 2 * ks, 1u);
                TC_COMMIT_MC_CG2(sb + OFF_XDONE(xs));
                TC_COMMIT_MC_CG2(sb + OFF_HDONE(hs));
                if (p == PPT - 1) TC_COMMIT_MC_CG2(sb + OFF_EPI1);   // D1 final
                if (++xs == NXS) { xs = 0; xph ^= 1; }
                if (++hs == NHS) { hs = 0; hph ^= 1; }
            }
        }
    } else if (wid == 1 && lid == 0) {
        // ---------------- TMA producer (both ranks) ----------------
        int xs = 0, xph = 0, hs = 0, hph = 0;
        int filled = 0;
        for (int j = 0; j < cnt; j++) {
            int m0 = (c + NPAIR * j) * 256;
            for (int k = 0; k < PPT; k++) {
                // X fill: 2 SW128 sub-tiles (k*64 and k*64+32)
                if (filled >= NXS)
                    MBAR_WAIT(sb + OFF_XDONE(xs), xph ^ 1);
                if (rank == 0)
                    MBAR_EXPECT_TX(sb + OFF_XFULL(xs), EXPECT_X);
                TMA3D_CG2(sb + OFF_XS(xs),         &mx, k * KC,      m0 + rank * 128, 0,
                          sb + OFF_XFULL(xs));
                TMA3D_CG2(sb + OFF_XS(xs) + 16384, &mx, k * KC + 32, m0 + rank * 128, 0,
                          sb + OFF_XFULL(xs));
                // H fill: 2 pre-swizzled 32KB segments (kc32 = 2k, 2k+1)
                if (filled >= NHS)
                    MBAR_WAIT(sb + OFF_HDONE(hs), hph ^ 1);
                if (rank == 0)
                    MBAR_EXPECT_TX(sb + OFF_HFULL(hs), EXPECT_H);
                TMA2D_CG2(sb + OFF_HS(hs),         &mh, 0, (4 * k + rank) * 32,
                          sb + OFF_HFULL(hs));
                TMA2D_CG2(sb + OFF_HS(hs) + 32768, &mh, 0, (4 * k + 2 + rank) * 32,
                          sb + OFF_HFULL(hs));
                filled++;
                if (++xs == NXS) { xs = 0; xph ^= 1; }
                if (++hs == NHS) { hs = 0; hph ^= 1; }
            }
        }
    } else if (wid >= 2) {
        // ---------------- epilogue warps (2..9, both ranks) ----------------
        // 2 warps per subpartition: sp = wid&3; wid<6 -> chunks 0..3,
        // wid>=6 -> chunks 4..7 (of 8 chunks per 256-col half).
        int sp = wid & 3;
        int ch0 = (wid >= 6) ? 4 : 0;
        const float4* bsm = reinterpret_cast<const float4*>(smem_raw + OFF_BIAS);
        for (int j = 0; j < cnt; j++) {
            size_t row = (size_t)((c + NPAIR * j) * 256 + rank * 128 + sp * 32 + lid);
            float* orow = out + row * N_F;
#pragma unroll
            for (int half = 0; half < 2; half++) {
                MBAR_WAIT(sb + (half ? OFF_EPI1 : OFF_EPI0), j & 1);
                asm volatile("tcgen05.fence::after_thread_sync;" ::: "memory");
                int base = half * 256 + ch0 * 32;
                uint32_t rg[2][32];
                LDTM_X32(rg[0], tmem + base);
#pragma unroll
                for (int cc = 0; cc < 4; cc++) {
                    asm volatile("tcgen05.wait::ld.sync.aligned;" ::: "memory");
                    if (cc < 3)
                        LDTM_X32(rg[(cc + 1) & 1], tmem + base + (cc + 1) * 32);
                    if (cc == 3) {
                        // all 4 chunks in regs -> release dispatcher
                        asm volatile("tcgen05.fence::before_thread_sync;" ::: "memory");
                        if (lid == 0) {
                            uint32_t dfrb = sb + (half ? OFF_DFREE1 : OFF_DFREE0);
                            if (rank == 0) { MBAR_ARRIVE(dfrb); }
                            else           { MBAR_ARRIVE_CLUSTER0(dfrb); }
                        }
                    }
                    const uint32_t* r = rg[cc & 1];
                    int c0 = base + cc * 32;
#pragma unroll
                    for (int q = 0; q < 8; q++) {
                        float4 bv = bsm[(c0 >> 2) + q];
                        float4 v;
                        v.x = __uint_as_float(r[q * 4 + 0]) + bv.x;
                        v.y = __uint_as_float(r[q * 4 + 1]) + bv.y;
                        v.z = __uint_as_float(r[q * 4 + 2]) + bv.z;
                        v.w = __uint_as_float(r[q * 4 + 3]) + bv.w;
                        *reinterpret_cast<float4*>(orow + c0 + q * 4) = v;
                    }
                }
            }
        }
    }

    __syncthreads();
    // Peer may still be MMA-reading our SMEM / arriving on our barriers.
    CLUSTER_SYNC();
    if (wid == 0) {
        asm volatile("tcgen05.dealloc.cta_group::2.sync.aligned.b32 %0, %1;"
                     :: "r"(tmem), "r"(512));
    }

#else
    // =================== SIMT fp32 fallback (non-'a' pass) ================
    (void)mx; (void)mh;
    extern __shared__ char smem_raw[];
    float* Xs = reinterpret_cast<float*>(smem_raw);          // [128][33]
    float* Hs = Xs + 128 * 33;                               // [64][33]

    int tid = threadIdx.x;
    int ty = tid >> 4, tx = tid & 15;   // ty 0..19; compute only ty<16

    for (int g = bid; g < ntiles; g += GRID) {
        int m0 = (g >> 1) * 256;
        int nb = g & 1;
        for (int half = 0; half < 2; half++) {
            int m0h = m0 + half * 128;
            for (int nc = 0; nc < 4; nc++) {
                int col0 = nb * 256 + nc * 64;
                float acc[8][4];
#pragma unroll
                for (int i = 0; i < 8; i++)
#pragma unroll
                    for (int j = 0; j < 4; j++) acc[i][j] = 0.f;

                for (int kb = 0; kb < 16; kb++) {
                    for (int idx = tid; idx < 128 * 32; idx += NTHREADS) {
                        int r = idx >> 5, k = idx & 31;
                        Xs[r * 33 + k] = x[(size_t)(m0h + r) * N_F + kb * 32 + k];
                    }
                    for (int idx = tid; idx < 64 * 32; idx += NTHREADS) {
                        int r = idx >> 5, k = idx & 31;
                        Hs[r * 33 + k] = g_H[(size_t)(col0 + r) * N_F + kb * 32 + k];
                    }
                    __syncthreads();
                    if (ty < 16) {
#pragma unroll
                        for (int k = 0; k < 32; k++) {
                            float a8[8], b4[4];
#pragma unroll
                            for (int i = 0; i < 8; i++) a8[i] = Xs[(ty * 8 + i) * 33 + k];
#pragma unroll
                            for (int j = 0; j < 4; j++) b4[j] = Hs[(tx * 4 + j) * 33 + k];
#pragma unroll
                            for (int i = 0; i < 8; i++)
#pragma unroll
                                for (int j = 0; j < 4; j++)
                                    acc[i][j] = fmaf(a8[i], b4[j], acc[i][j]);
                        }
                    }
                    __syncthreads();
                }
                if (ty < 16) {
#pragma unroll
                    for (int i = 0; i < 8; i++)
#pragma unroll
                        for (int j = 0; j < 4; j++) {
                            int col = col0 + tx * 4 + j;
                            out[(size_t)(m0h + ty * 8 + i) * N_F + col] = acc[i][j] + bias[col];
                        }
                }
            }
        }
    }
#endif
}

// ---------------------------------------------------------------------------
// Host launcher
// ---------------------------------------------------------------------------
typedef CUresult (*PFN_encodeTiled)(
    CUtensorMap*, CUtensorMapDataType, cuuint32_t, void*,
    const cuuint64_t*, const cuuint64_t*, const cuuint32_t*, const cuuint32_t*,
    CUtensorMapInterleave, CUtensorMapSwizzle, CUtensorMapL2promotion,
    CUtensorMapFloatOOBfill);

extern "C" void kernel_launch(void* const* d_in, const int* in_sizes, int n_in,
                              void* d_out, int out_size) {
    const float* x    = (const float*)d_in[0];
    const float* A    = (const float*)d_in[1];
    const float* S    = (const float*)d_in[2];
    const float* bias = (const float*)d_in[3];
    float* out = (float*)d_out;

    long Mrows = (long)in_sizes[0] / N_F;   // 131072
    int ntiles = (int)(Mrows / 256) * 2;    // fallback path only

    build_H<<<N_F, N_F>>>(A, S);

    void* hswptr = nullptr;
    cudaGetSymbolAddress(&hswptr, g_Hsw);

    // Resolve cuTensorMapEncodeTiled via the runtime (no -lcuda needed).
    PFN_encodeTiled enc = nullptr;
    {
        cudaDriverEntryPointQueryResult st;
        cudaGetDriverEntryPointByVersion("cuTensorMapEncodeTiled", (void**)&enc,
                                         12050, cudaEnableDefault, &st);
    }

    CUtensorMap mx{}, mh{};
    if (enc) {
        {
            // X: 3D [k=512][m=131072][1], box {32,128,1}, SW128
            cuuint64_t dims[3]    = {(cuuint64_t)N_F, (cuuint64_t)Mrows, 1};
            cuuint64_t strides[2] = {(cuuint64_t)N_F * 4, (cuuint64_t)N_F * 4 * Mrows};
            cuuint32_t box[3]     = {32, 128, 1};
            cuuint32_t es[3]      = {1, 1, 1};
            enc(&mx, CU_TENSOR_MAP_DATA_TYPE_FLOAT32, 3, (void*)x,
                dims, strides, box, es,
                CU_TENSOR_MAP_INTERLEAVE_NONE, CU_TENSOR_MAP_SWIZZLE_128B,
                CU_TENSOR_MAP_L2_PROMOTION_L2_128B, CU_TENSOR_MAP_FLOAT_OOB_FILL_NONE);
        }
        {
            // H (pre-swizzled image): 2D [256 floats/row][1024 rows of 1024B],
            // box {256, 32} = one 32KB (kc32,rank) segment, SWIZZLE_NONE.
            cuuint64_t dims[2]    = {256, 1024};
            cuuint64_t strides[1] = {1024};
            cuuint32_t box[2]     = {256, 32};
            cuuint32_t es[2]      = {1, 1};
            enc(&mh, CU_TENSOR_MAP_DATA_TYPE_FLOAT32, 2, hswptr,
                dims, strides, box, es,
                CU_TENSOR_MAP_INTERLEAVE_NONE, CU_TENSOR_MAP_SWIZZLE_NONE,
                CU_TENSOR_MAP_L2_PROMOTION_L2_128B, CU_TENSOR_MAP_FLOAT_OOB_FILL_NONE);
        }
    }

    cudaFuncSetAttribute(phm_gemm, cudaFuncAttributeMaxDynamicSharedMemorySize, SMEM_BYTES);
    phm_gemm<<<GRID, NTHREADS, SMEM_BYTES>>>(x, bias, out, ntiles, mx, mh);
}

// round 17
// speedup vs baseline: 1.0769x; 1.0208x over previous
#include <cuda_runtime.h>
#include <cuda.h>
#include <cstdint>

// ============================================================================
// PHM8Linear: out[131072,512] = X[131072,512] @ H[512,512]^T + bias
// H[a*64+b][c*64+d] = sum_i A[i,a,c] * S[i,b,d]
// tcgen05 TF32 cta_group::2 SS GEMM, persistent grid=148, cluster (2,1,1).
// R17: r16 (dual TMA producers: warp1=X ring, warp2=H ring; 8 epilogue warps
// 3-10 with ping-pong LDTM, bias in smem) with the TMEM subpartition mapping
// FIXED: tcgen05.ld reads the issuing warp's own subpartition (wid & 3), so
// sp = wid & 3 and chunk-half = (wid >= 7). Mainloop: KC=64/position,
// X ring 3x32KB, H ring 2x64KB (pre-swizzled images), epilogue split per
// N-half with lookahead-2 D0 burst. X raw fp32 (HW tf32 truncate).
// ============================================================================

#define N_F    512
#define KC     64          // K elems per position (2 x SW128 rows)
#define NXS    3           // X ring depth
#define NHS    2           // H ring depth
#define GRID   148
#define NPAIR  74
#define M_TILES 512        // 131072/256
#define PPT    8           // positions per tile (512/KC)
#define NTHREADS 352

__device__ float g_H[N_F * N_F];     // row-major H (SIMT fallback only)
__device__ float g_Hsw[N_F * N_F];   // pre-swizzled SW128 images: [kc32][rank][b][16KB]

#if defined(__CUDA_ARCH__) && (defined(__CUDA_ARCH_FEAT_SM103_ALL) || \
    defined(__CUDA_ARCH_FEAT_SM100_ALL) || defined(__CUDA_ARCH_FEAT_SM101_ALL))
#define HAS_TCGEN05 1
#else
#define HAS_TCGEN05 0
#endif

// ---------------- smem layout (dynamic), tcgen05 path ----------------
#define OFF_TPTR    0
#define OFF_XFULL(s) (8 + 8 * (s))       // 3
#define OFF_XDONE(s) (40 + 8 * (s))      // 3
#define OFF_HFULL(s) (72 + 8 * (s))      // 2
#define OFF_HDONE(s) (96 + 8 * (s))      // 2
#define OFF_EPI0    120
#define OFF_EPI1    128
#define OFF_DFREE0  136
#define OFF_DFREE1  144
#define OFF_BIAS    256                      // 512 floats = 2KB (cached bias)
#define OFF_XS(s)   (3072 + (s) * 32768)     // 3 x 32KB (sub0 16KB | sub1 16KB)
#define OFF_HS(s)   (101376 + (s) * 65536)   // 2 x 64KB (kcA H0|H1, kcB H0|H1)
#define SMEM_BYTES  232448                   // 227KB opt-in max
#define EXPECT_X    65536u    // 32KB x 2 CTAs onto leader's barrier
#define EXPECT_H    131072u   // 64KB x 2 CTAs

// idesc: kind::tf32, D=F32(1<<4), A=TF32(2<<7), B=TF32(2<<10), N=256, M=256
#define IDESC_TF32_CG2 ((1u << 4) | (2u << 7) | (2u << 10) | ((256u / 8u) << 17) | ((256u / 16u) << 24))

// K-major SW128 smem descriptor base: layout=SW128(2), version=1, SBO=64, LBO=1
static __device__ __host__ constexpr uint64_t DESC_BASE_SW128 =
    (uint64_t(2) << 61) | (uint64_t(1) << 46) | (uint64_t(64) << 32) | (uint64_t(1) << 16);

__device__ __forceinline__ uint32_t s2u(const void* p) {
    uint32_t a;
    asm("{ .reg .u64 t; cvta.to.shared.u64 t, %1; cvt.u32.u64 %0, t; }" : "=r"(a) : "l"(p));
    return a;
}

#define MBAR_INIT(addr, cnt) \
    asm volatile("mbarrier.init.shared.b64 [%0], %1;" :: "r"(addr), "r"(cnt) : "memory")

#define MBAR_ARRIVE(addr) \
    asm volatile("mbarrier.arrive.shared.b64 _, [%0];" :: "r"(addr) : "memory")

// Arrive on the same-offset mbarrier in cluster CTA rank 0.
#define MBAR_ARRIVE_CLUSTER0(addr)                                             \
    asm volatile("{\n\t.reg .b32 ra;\n\t"                                      \
        "mapa.shared::cluster.u32 ra, %0, %1;\n\t"                             \
        "mbarrier.arrive.shared::cluster.b64 _, [ra];\n\t}"                    \
        :: "r"(addr), "r"(0) : "memory")

#define MBAR_EXPECT_TX(addr, bytes) \
    asm volatile("mbarrier.arrive.expect_tx.shared.b64 _, [%0], %1;" :: "r"(addr), "r"(bytes) : "memory")

#define MBAR_WAIT_SCOPE(addr, parity, SCOPE) do {                              \
    uint32_t _mb = (addr); uint32_t _ph = (parity); uint32_t _dn;              \
    asm volatile("{\n\t.reg .pred p;\n\t"                                      \
        "mbarrier.try_wait.parity.acquire." SCOPE ".shared::cta.b64 p, [%1], %2;\n\t" \
        "selp.b32 %0, 1, 0, p;\n\t}" : "=r"(_dn) : "r"(_mb), "r"(_ph) : "memory"); \
    while (!_dn) {                                                             \
        asm volatile("{\n\t.reg .pred p;\n\t"                                  \
            "mbarrier.try_wait.parity.acquire." SCOPE ".shared::cta.b64 p, [%1], %2, 0x989680;\n\t" \
            "selp.b32 %0, 1, 0, p;\n\t}" : "=r"(_dn) : "r"(_mb), "r"(_ph) : "memory"); \
    }                                                                          \
} while (0)

#define MBAR_WAIT(addr, parity)     MBAR_WAIT_SCOPE(addr, parity, "cta")
#define MBAR_WAIT_CLU(addr, parity) MBAR_WAIT_SCOPE(addr, parity, "cluster")

// cta_group::2 TMA (3D): completes on leader's barrier (bit 24 cleared).
#define TMA3D_CG2(smem, map, cx, cy, cz, mbar)                                 \
    asm volatile("{\n\t.reg .b32 lb;\n\t"                                      \
        "and.b32 lb, %5, 0xFEFFFFFF;\n\t"                                      \
        "cp.async.bulk.tensor.3d.cta_group::2.shared::cluster.global"          \
        ".tile.mbarrier::complete_tx::bytes [%0], [%1, {%2, %3, %4}], [lb];\n\t}" \
        :: "r"(smem), "l"(map), "r"(cx), "r"(cy), "r"(cz), "r"(mbar) : "memory")

// cta_group::2 TMA (2D) — used for the pre-swizzled H fetch.
#define TMA2D_CG2(smem, map, cx, cy, mbar)                                     \
    asm volatile("{\n\t.reg .b32 lb;\n\t"                                      \
        "and.b32 lb, %4, 0xFEFFFFFF;\n\t"                                      \
        "cp.async.bulk.tensor.2d.cta_group::2.shared::cluster.global"          \
        ".tile.mbarrier::complete_tx::bytes [%0], [%1, {%2, %3}], [lb];\n\t}"  \
        :: "r"(smem), "l"(map), "r"(cx), "r"(cy), "r"(mbar) : "memory")

// cta_group::2 tf32 MMA (leader issues; A/B split across the CTA pair)
#define MMA_TF32_CG2(dst, adsc, bdsc, en)                                      \
    asm volatile("{\n\t.reg .pred p;\n\tsetp.ne.u32 p, %5, 0;\n\t"             \
        "tcgen05.mma.cta_group::2.kind::tf32 [%0], %1, %2, %3, "               \
        "{%4,%4,%4,%4,%4,%4,%4,%4}, p;\n\t}"                                   \
        :: "r"(dst), "l"(adsc), "l"(bdsc), "r"(IDESC_TF32_CG2), "r"(0u), "r"(en) : "memory")

#define TC_COMMIT_MC_CG2(mbar)                                                 \
    asm volatile("tcgen05.commit.cta_group::2.mbarrier::arrive::one.shared::cluster.multicast::cluster.b64 [%0], %1;" \
        :: "r"(mbar), "h"((uint16_t)3) : "memory")

#define CLUSTER_SYNC() do {                                                    \
    asm volatile("barrier.cluster.arrive.aligned;" ::: "memory");              \
    asm volatile("barrier.cluster.wait.aligned;" ::: "memory");                \
} while (0)

#define LDTM_X32(r, tmem_addr)                                                 \
    asm volatile(                                                              \
        "tcgen05.ld.sync.aligned.32x32b.x32.b32 "                              \
        "{%0, %1, %2, %3, %4, %5, %6, %7, "                                    \
        " %8, %9, %10, %11, %12, %13, %14, %15, "                              \
        " %16, %17, %18, %19, %20, %21, %22, %23, "                            \
        " %24, %25, %26, %27, %28, %29, %30, %31}, [%32];"                     \
        : "=r"((r)[0]),  "=r"((r)[1]),  "=r"((r)[2]),  "=r"((r)[3]),           \
          "=r"((r)[4]),  "=r"((r)[5]),  "=r"((r)[6]),  "=r"((r)[7]),           \
          "=r"((r)[8]),  "=r"((r)[9]),  "=r"((r)[10]), "=r"((r)[11]),          \
          "=r"((r)[12]), "=r"((r)[13]), "=r"((r)[14]), "=r"((r)[15]),          \
          "=r"((r)[16]), "=r"((r)[17]), "=r"((r)[18]), "=r"((r)[19]),          \
          "=r"((r)[20]), "=r"((r)[21]), "=r"((r)[22]), "=r"((r)[23]),          \
          "=r"((r)[24]), "=r"((r)[25]), "=r"((r)[26]), "=r"((r)[27]),          \
          "=r"((r)[28]), "=r"((r)[29]), "=r"((r)[30]), "=r"((r)[31])           \
        : "r"(tmem_addr))

// ---------------------------------------------------------------------------
// H precompute: H[r=a*64+b][k=c*64+d] = sum_i A[i,a,c]*S[i,b,d], RN->tf32.
// g_Hsw: SW128 smem byte image, segmented [kc32][rank] (32KB each:
// block0 16KB | block1 16KB); linear TMA reproduces the swizzled image.
// ---------------------------------------------------------------------------
__global__ void build_H(const float* __restrict__ A, const float* __restrict__ S) {
    int r = blockIdx.x;     // 0..511
    int k = threadIdx.x;    // 0..511
    int a = r >> 6, bb = r & 63, c = k >> 6, d = k & 63;
    float acc = 0.f;
#pragma unroll
    for (int i = 0; i < 8; i++)
        acc = fmaf(A[i * 64 + a * 8 + c], S[i * 4096 + bb * 64 + d], acc);
    uint32_t t;
    asm("cvt.rna.tf32.f32 %0, %1;" : "=r"(t) : "f"(acc));
    float v = __uint_as_float(t);
    g_H[r * N_F + k] = v;

    int kc  = k >> 5;            // 32-wide k-chunk 0..15
    int col = k & 31;
    int b   = r >> 8;            // column block 0/1
    int rib = r & 255;
    int rr  = rib >> 7;          // rank half
    int row = rib & 127;
    uint32_t off = (uint32_t)(kc * 2 + rr) * 32768u + (uint32_t)b * 16384u;
    uint32_t bo  = (uint32_t)(row * 128 + col * 4);
    bo = bo ^ ((bo >> 3) & 0x70);            // SW128 swizzle
    *reinterpret_cast<float*>(reinterpret_cast<char*>(g_Hsw) + off + bo) = v;
}

// ---------------------------------------------------------------------------
// Main GEMM kernel
// ---------------------------------------------------------------------------
__global__ void __launch_bounds__(NTHREADS, 1) __cluster_dims__(2, 1, 1) phm_gemm(
    const float* __restrict__ x,
    const float* __restrict__ bias, float* __restrict__ out,
    int ntiles,
    const __grid_constant__ CUtensorMap mx,
    const __grid_constant__ CUtensorMap mh)
{
    int bid = blockIdx.x;

#if HAS_TCGEN05
    // =================== tcgen05 TF32 cg2 path (sm_103a) ==================
    (void)x; (void)ntiles;
    extern __shared__ char smem_raw[];
    uint32_t sb = s2u(smem_raw);
    int tid = threadIdx.x, wid = tid >> 5, lid = tid & 31;

    int c    = bid >> 1;        // pair id (0..73)
    int rank = bid & 1;         // cluster rank
    int cnt  = 1 + (M_TILES - 1 - c) / NPAIR;   // tiles for this pair

    if (wid == 0) {
        asm volatile("tcgen05.alloc.cta_group::2.sync.aligned.shared::cta.b32 [%0], %1;"
                     :: "r"(sb + OFF_TPTR), "r"(512) : "memory");
        asm volatile("tcgen05.relinquish_alloc_permit.cta_group::2.sync.aligned;");
    }
    if (tid == 0) {
#pragma unroll
        for (int s = 0; s < NXS; s++) {
            MBAR_INIT(sb + OFF_XFULL(s), 1);
            MBAR_INIT(sb + OFF_XDONE(s), 1);
        }
#pragma unroll
        for (int s = 0; s < NHS; s++) {
            MBAR_INIT(sb + OFF_HFULL(s), 1);
            MBAR_INIT(sb + OFF_HDONE(s), 1);
        }
        MBAR_INIT(sb + OFF_EPI0, 1);
        MBAR_INIT(sb + OFF_EPI1, 1);
        MBAR_INIT(sb + OFF_DFREE0, 16);      // 8 epilogue warps x 2 CTAs
        MBAR_INIT(sb + OFF_DFREE1, 16);
    }
    // Cache bias in smem (512 floats)
    if (tid < 128)
        reinterpret_cast<float4*>(smem_raw + OFF_BIAS)[tid] =
            reinterpret_cast<const float4*>(bias)[tid];
    __syncthreads();
    uint32_t tmem;
    asm volatile("ld.shared.b32 %0, [%1];" : "=r"(tmem) : "r"(sb + OFF_TPTR));

    // All mbarriers live in both CTAs before any cross-CTA TMA/commit.
    CLUSTER_SYNC();

    if (wid == 0 && lid == 0 && rank == 0) {
        // ---------------- MMA dispatcher (leader only) ----------------
        uint64_t dX[NXS], dH[NHS];
#pragma unroll
        for (int s = 0; s < NXS; s++)
            dX[s] = DESC_BASE_SW128 | (((sb + OFF_XS(s)) >> 4) & 0x3FFF);
#pragma unroll
        for (int s = 0; s < NHS; s++)
            dH[s] = DESC_BASE_SW128 | (((sb + OFF_HS(s)) >> 4) & 0x3FFF);

        int xs = 0, xph = 0, hs = 0, hph = 0;
        for (int j = 0; j < cnt; j++) {
            int sx[2], sh[2];
            // ---- phase A: positions 0..1, D0 MMAs (overlap epilogue D1 read)
            if (j > 0) {
                MBAR_WAIT(sb + OFF_DFREE0, (j - 1) & 1);
                asm volatile("tcgen05.fence::after_thread_sync;" ::: "memory");
            }
#pragma unroll
            for (int q = 0; q < 2; q++) {
                MBAR_WAIT_CLU(sb + OFF_XFULL(xs), xph);
                MBAR_WAIT_CLU(sb + OFF_HFULL(hs), hph);
#pragma unroll
                for (int ks = 0; ks < 4; ks++)
                    MMA_TF32_CG2(tmem, dX[xs] + 2 * ks, dH[hs] + 2 * ks, (q | ks) ? 1u : 0u);
#pragma unroll
                for (int ks = 0; ks < 4; ks++)
                    MMA_TF32_CG2(tmem, dX[xs] + 1024 + 2 * ks, dH[hs] + 2048 + 2 * ks, 1u);
                sx[q] = xs; sh[q] = hs;
                if (++xs == NXS) { xs = 0; xph ^= 1; }
                if (++hs == NHS) { hs = 0; hph ^= 1; }
            }
            // ---- phase B: D1 for positions 0..1 + done commits
            if (j > 0) {
                MBAR_WAIT(sb + OFF_DFREE1, (j - 1) & 1);
                asm volatile("tcgen05.fence::after_thread_sync;" ::: "memory");
            }
#pragma unroll
            for (int q = 0; q < 2; q++) {
#pragma unroll
                for (int ks = 0; ks < 4; ks++)
                    MMA_TF32_CG2(tmem + 256, dX[sx[q]] + 2 * ks, dH[sh[q]] + 1024 + 2 * ks, (q | ks) ? 1u : 0u);
#pragma unroll
                for (int ks = 0; ks < 4; ks++)
                    MMA_TF32_CG2(tmem + 256, dX[sx[q]] + 1024 + 2 * ks, dH[sh[q]] + 3072 + 2 * ks, 1u);
                TC_COMMIT_MC_CG2(sb + OFF_XDONE(sx[q]));
                TC_COMMIT_MC_CG2(sb + OFF_HDONE(sh[q]));
            }
            // ---- steady positions 2..7
            for (int p = 2; p < PPT; p++) {
                MBAR_WAIT_CLU(sb + OFF_XFULL(xs), xph);
                MBAR_WAIT_CLU(sb + OFF_HFULL(hs), hph);
#pragma unroll
                for (int ks = 0; ks < 4; ks++)
                    MMA_TF32_CG2(tmem, dX[xs] + 2 * ks, dH[hs] + 2 * ks, 1u);
#pragma unroll
                for (int ks = 0; ks < 4; ks++)
                    MMA_TF32_CG2(tmem, dX[xs] + 1024 + 2 * ks, dH[hs] + 2048 + 2 * ks, 1u);
                if (p == PPT - 1) TC_COMMIT_MC_CG2(sb + OFF_EPI0);   // D0 final
#pragma unroll
                for (int ks = 0; ks < 4; ks++)
                    MMA_TF32_CG2(tmem + 256, dX[xs] + 2 * ks, dH[hs] + 1024 + 2 * ks, 1u);
#pragma unroll
                for (int ks = 0; ks < 4; ks++)
                    MMA_TF32_CG2(tmem + 256, dX[xs] + 1024 + 2 * ks, dH[hs] + 3072 + 2 * ks, 1u);
                TC_COMMIT_MC_CG2(sb + OFF_XDONE(xs));
                TC_COMMIT_MC_CG2(sb + OFF_HDONE(hs));
                if (p == PPT - 1) TC_COMMIT_MC_CG2(sb + OFF_EPI1);   // D1 final
                if (++xs == NXS) { xs = 0; xph ^= 1; }
                if (++hs == NHS) { hs = 0; hph ^= 1; }
            }
        }
    } else if (wid == 1 && lid == 0) {
        // ---------------- X producer (both ranks) ----------------
        int xs = 0, xph = 0, filled = 0;
        for (int j = 0; j < cnt; j++) {
            int m0 = (c + NPAIR * j) * 256;
            for (int k = 0; k < PPT; k++) {
                if (filled >= NXS)
                    MBAR_WAIT(sb + OFF_XDONE(xs), xph ^ 1);
                if (rank == 0)
                    MBAR_EXPECT_TX(sb + OFF_XFULL(xs), EXPECT_X);
                TMA3D_CG2(sb + OFF_XS(xs),         &mx, k * KC,      m0 + rank * 128, 0,
                          sb + OFF_XFULL(xs));
                TMA3D_CG2(sb + OFF_XS(xs) + 16384, &mx, k * KC + 32, m0 + rank * 128, 0,
                          sb + OFF_XFULL(xs));
                filled++;
                if (++xs == NXS) { xs = 0; xph ^= 1; }
            }
        }
    } else if (wid == 2 && lid == 0) {
        // ---------------- H producer (both ranks) ----------------
        int hs = 0, hph = 0, filled = 0;
        for (int j = 0; j < cnt; j++) {
            for (int k = 0; k < PPT; k++) {
                if (filled >= NHS)
                    MBAR_WAIT(sb + OFF_HDONE(hs), hph ^ 1);
                if (rank == 0)
                    MBAR_EXPECT_TX(sb + OFF_HFULL(hs), EXPECT_H);
                TMA2D_CG2(sb + OFF_HS(hs),         &mh, 0, (4 * k + rank) * 32,
                          sb + OFF_HFULL(hs));
                TMA2D_CG2(sb + OFF_HS(hs) + 32768, &mh, 0, (4 * k + 2 + rank) * 32,
                          sb + OFF_HFULL(hs));
                filled++;
                if (++hs == NHS) { hs = 0; hph ^= 1; }
            }
        }
    } else if (wid >= 3) {
        // ---------------- epilogue warps (3..10, both ranks) ----------------
        // tcgen05.ld reads the issuing warp's OWN subpartition (wid & 3).
        // Warps 3..10 -> sp = {3,0,1,2,3,0,1,2}: each sp covered twice;
        // wid<7 -> chunks 0..3, wid>=7 -> chunks 4..7 (per 256-col half).
        int sp = wid & 3;
        int ch0 = (wid >= 7) ? 4 : 0;
        const float4* bsm = reinterpret_cast<const float4*>(smem_raw + OFF_BIAS);
        for (int j = 0; j < cnt; j++) {
            size_t row = (size_t)((c + NPAIR * j) * 256 + rank * 128 + sp * 32 + lid);
            float* orow = out + row * N_F;
#pragma unroll
            for (int half = 0; half < 2; half++) {
                MBAR_WAIT(sb + (half ? OFF_EPI1 : OFF_EPI0), j & 1);
                asm volatile("tcgen05.fence::after_thread_sync;" ::: "memory");
                int base = half * 256 + ch0 * 32;
                uint32_t rg[2][32];
                LDTM_X32(rg[0], tmem + base);
#pragma unroll
                for (int cc = 0; cc < 4; cc++) {
                    asm volatile("tcgen05.wait::ld.sync.aligned;" ::: "memory");
                    if (cc < 3)
                        LDTM_X32(rg[(cc + 1) & 1], tmem + base + (cc + 1) * 32);
                    if (cc == 3) {
                        // all 4 chunks in regs -> release dispatcher
                        asm volatile("tcgen05.fence::before_thread_sync;" ::: "memory");
                        if (lid == 0) {
                            uint32_t dfrb = sb + (half ? OFF_DFREE1 : OFF_DFREE0);
                            if (rank == 0) { MBAR_ARRIVE(dfrb); }
                            else           { MBAR_ARRIVE_CLUSTER0(dfrb); }
                        }
                    }
                    const uint32_t* r = rg[cc & 1];
                    int c0 = base + cc * 32;
#pragma unroll
                    for (int q = 0; q < 8; q++) {
                        float4 bv = bsm[(c0 >> 2) + q];
                        float4 v;
                        v.x = __uint_as_float(r[q * 4 + 0]) + bv.x;
                        v.y = __uint_as_float(r[q * 4 + 1]) + bv.y;
                        v.z = __uint_as_float(r[q * 4 + 2]) + bv.z;
                        v.w = __uint_as_float(r[q * 4 + 3]) + bv.w;
                        *reinterpret_cast<float4*>(orow + c0 + q * 4) = v;
                    }
                }
            }
        }
    }

    __syncthreads();
    // Peer may still be MMA-reading our SMEM / arriving on our barriers.
    CLUSTER_SYNC();
    if (wid == 0) {
        asm volatile("tcgen05.dealloc.cta_group::2.sync.aligned.b32 %0, %1;"
                     :: "r"(tmem), "r"(512));
    }

#else
    // =================== SIMT fp32 fallback (non-'a' pass) ================
    (void)mx; (void)mh;
    extern __shared__ char smem_raw[];
    float* Xs = reinterpret_cast<float*>(smem_raw);          // [128][33]
    float* Hs = Xs + 128 * 33;                               // [64][33]

    int tid = threadIdx.x;
    int ty = tid >> 4, tx = tid & 15;   // compute only ty<16

    for (int g = bid; g < ntiles; g += GRID) {
        int m0 = (g >> 1) * 256;
        int nb = g & 1;
        for (int half = 0; half < 2; half++) {
            int m0h = m0 + half * 128;
            for (int nc = 0; nc < 4; nc++) {
                int col0 = nb * 256 + nc * 64;
                float acc[8][4];
#pragma unroll
                for (int i = 0; i < 8; i++)
#pragma unroll
                    for (int j = 0; j < 4; j++) acc[i][j] = 0.f;

                for (int kb = 0; kb < 16; kb++) {
                    for (int idx = tid; idx < 128 * 32; idx += NTHREADS) {
                        int r = idx >> 5, k = idx & 31;
                        Xs[r * 33 + k] = x[(size_t)(m0h + r) * N_F + kb * 32 + k];
                    }
                    for (int idx = tid; idx < 64 * 32; idx += NTHREADS) {
                        int r = idx >> 5, k = idx & 31;
                        Hs[r * 33 + k] = g_H[(size_t)(col0 + r) * N_F + kb * 32 + k];
                    }
                    __syncthreads();
                    if (ty < 16) {
#pragma unroll
                        for (int k = 0; k < 32; k++) {
                            float a8[8], b4[4];
#pragma unroll
                            for (int i = 0; i < 8; i++) a8[i] = Xs[(ty * 8 + i) * 33 + k];
#pragma unroll
                            for (int j = 0; j < 4; j++) b4[j] = Hs[(tx * 4 + j) * 33 + k];
#pragma unroll
                            for (int i = 0; i < 8; i++)
#pragma unroll
                                for (int j = 0; j < 4; j++)
                                    acc[i][j] = fmaf(a8[i], b4[j], acc[i][j]);
                        }
                    }
                    __syncthreads();
                }
                if (ty < 16) {
#pragma unroll
                    for (int i = 0; i < 8; i++)
#pragma unroll
                        for (int j = 0; j < 4; j++) {
                            int col = col0 + tx * 4 + j;
                            out[(size_t)(m0h + ty * 8 + i) * N_F + col] = acc[i][j] + bias[col];
                        }
                }
            }
        }
    }
#endif
}

// ---------------------------------------------------------------------------
// Host launcher
// ---------------------------------------------------------------------------
typedef CUresult (*PFN_encodeTiled)(
    CUtensorMap*, CUtensorMapDataType, cuuint32_t, void*,
    const cuuint64_t*, const cuuint64_t*, const cuuint32_t*, const cuuint32_t*,
    CUtensorMapInterleave, CUtensorMapSwizzle, CUtensorMapL2promotion,
    CUtensorMapFloatOOBfill);

extern "C" void kernel_launch(void* const* d_in, const int* in_sizes, int n_in,
                              void* d_out, int out_size) {
    const float* x    = (const float*)d_in[0];
    const float* A    = (const float*)d_in[1];
    const float* S    = (const float*)d_in[2];
    const float* bias = (const float*)d_in[3];
    float* out = (float*)d_out;

    long Mrows = (long)in_sizes[0] / N_F;   // 131072
    int ntiles = (int)(Mrows / 256) * 2;    // fallback path only

    build_H<<<N_F, N_F>>>(A, S);

    void* hswptr = nullptr;
    cudaGetSymbolAddress(&hswptr, g_Hsw);

    // Resolve cuTensorMapEncodeTiled via the runtime (no -lcuda needed).
    PFN_encodeTiled enc = nullptr;
    {
        cudaDriverEntryPointQueryResult st;
        cudaGetDriverEntryPointByVersion("cuTensorMapEncodeTiled", (void**)&enc,
                                         12050, cudaEnableDefault, &st);
    }

    CUtensorMap mx{}, mh{};
    if (enc) {
        {
            // X: 3D [k=512][m=131072][1], box {32,128,1}, SW128
            cuuint64_t dims[3]    = {(cuuint64_t)N_F, (cuuint64_t)Mrows, 1};
            cuuint64_t strides[2] = {(cuuint64_t)N_F * 4, (cuuint64_t)N_F * 4 * Mrows};
            cuuint32_t box[3]     = {32, 128, 1};
            cuuint32_t es[3]      = {1, 1, 1};
            enc(&mx, CU_TENSOR_MAP_DATA_TYPE_FLOAT32, 3, (void*)x,
                dims, strides, box, es,
                CU_TENSOR_MAP_INTERLEAVE_NONE, CU_TENSOR_MAP_SWIZZLE_128B,
                CU_TENSOR_MAP_L2_PROMOTION_L2_128B, CU_TENSOR_MAP_FLOAT_OOB_FILL_NONE);
        }
        {
            // H (pre-swizzled image): 2D [256 floats/row][1024 rows of 1024B],
            // box {256, 32} = one 32KB (kc32,rank) segment, SWIZZLE_NONE.
            cuuint64_t dims[2]    = {256, 1024};
            cuuint64_t strides[1] = {1024};
            cuuint32_t box[2]     = {256, 32};
            cuuint32_t es[2]      = {1, 1};
            enc(&mh, CU_TENSOR_MAP_DATA_TYPE_FLOAT32, 2, hswptr,
                dims, strides, box, es,
                CU_TENSOR_MAP_INTERLEAVE_NONE, CU_TENSOR_MAP_SWIZZLE_NONE,
                CU_TENSOR_MAP_L2_PROMOTION_L2_128B, CU_TENSOR_MAP_FLOAT_OOB_FILL_NONE);
        }
    }

    cudaFuncSetAttribute(phm_gemm, cudaFuncAttributeMaxDynamicSharedMemorySize, SMEM_BYTES);
    phm_gemm<<<GRID, NTHREADS, SMEM_BYTES>>>(x, bias, out, ntiles, mx, mh);
}